// round 11
// baseline (speedup 1.0000x reference)
#include <cuda_runtime.h>
#include <cuda_fp16.h>
#include <cstdint>

// ============================================================================
// LocationAwareAttention  B=32, S=2048, D=512   (family-common PTX only:
// mma.sync + ldmatrix + cp.async — NO tcgen05, target is sm_103)
//
// R11: fp16-accumulator mma (2x legacy-path rate), accumulated in fp16 only
// within one K=64 chunk (4 chained mma), then added into fp32 accumulators.
// Model: HMMA.f32 rt ~10.4 cyc/SMSP (R2/R4/R10 fit) -> tensor time halves.
// Error budget: +~2e-4 abs on scores -> rel_err ~3-5e-4, inside 1e-3.
// Everything else = R10-proven (warp-autonomous pipeline, periphery 34us).
// Output: d_out = [ctx (B*D) | align (B*S)] fp32
// ============================================================================

#define BB 32
#define SS 2048
#define DD 512

__device__ __half g_wvt[DD * DD];     // w_v^T [n][k] fp16
__device__ float  g_qw[BB * DD];      // q@w_q + bias + conv_b  (atomic-built)
__device__ float  g_scores[BB * SS];

// ---------------- SMEM layout (bytes) ----------------
#define SM_A    0                      // 8 chunks x (64x64 fp16, swizzled) = 64KB
#define SM_B    65536                  // 8 warps x 2 stages x 8KB = 128KB
#define SM_QWB  196608
#define SM_CW0  198656
#define SM_CW1  200704
#define SM_CW2  202752
#define SM_SW   204800
#define SM_E0   206848
#define SM_E1   207104
#define SM_E2   207360
#define SM_RED  207616                 // 64 x 8 f32
#define SM_TOT  209664

// ---------------- PTX helpers ----------------
__device__ __forceinline__ uint32_t s2u(const void* p) {
    uint32_t a;
    asm("{ .reg .u64 t; cvta.to.shared.u64 t, %1; cvt.u32.u64 %0, t; }"
        : "=r"(a) : "l"(p));
    return a;
}
__device__ __forceinline__ void cp16(uint32_t dst, const void* src) {
    asm volatile("cp.async.ca.shared.global [%0], [%1], 16;"
                 :: "r"(dst), "l"(src) : "memory");
}
__device__ __forceinline__ void cp_commit() {
    asm volatile("cp.async.commit_group;" ::: "memory");
}
__device__ __forceinline__ void cp_wait0() {
    asm volatile("cp.async.wait_group 0;" ::: "memory");
}
__device__ __forceinline__ void cp_wait1() {
    asm volatile("cp.async.wait_group 1;" ::: "memory");
}
__device__ __forceinline__ void ldsm4(uint32_t& r0, uint32_t& r1,
                                      uint32_t& r2, uint32_t& r3, uint32_t a) {
    asm volatile("ldmatrix.sync.aligned.m8n8.x4.shared.b16 {%0,%1,%2,%3}, [%4];"
                 : "=r"(r0), "=r"(r1), "=r"(r2), "=r"(r3) : "r"(a));
}
// fp16-accumulator mma: D,C = f16x2 pair (2 regs)
__device__ __forceinline__ void mma16816h(uint32_t& c0, uint32_t& c1,
                                          const uint32_t* a, const uint32_t* b) {
    asm volatile(
        "mma.sync.aligned.m16n8k16.row.col.f16.f16.f16.f16 "
        "{%0,%1}, {%2,%3,%4,%5}, {%6,%7}, {%0,%1};"
        : "+r"(c0), "+r"(c1)
        : "r"(a[0]), "r"(a[1]), "r"(a[2]), "r"(a[3]), "r"(b[0]), "r"(b[1]));
}
__device__ __forceinline__ uint32_t packh(__half a, __half b) {
    __half2 h2; h2.x = a; h2.y = b;
    return *(uint32_t*)&h2;
}
__device__ __forceinline__ uint32_t swz(uint32_t row, uint32_t colByte) {
    return row * 128u + (colByte ^ (((row) & 7u) << 4));
}

// ============================================================================
// zero: g_qw and ctx (both BB*DD) — must precede prep's atomics.
// ============================================================================
__global__ void zero_kernel(float* __restrict__ ctx) {
    int i = blockIdx.x * blockDim.x + threadIdx.x;
    if (i < BB * DD) { ctx[i] = 0.f; g_qw[i] = 0.f; }
}

// ============================================================================
// prep (R9-proven): 576 blocks x 256 threads.
// ============================================================================
__global__ void __launch_bounds__(256)
prep_kernel(const float* __restrict__ w_v,
            const float* __restrict__ query,
            const float* __restrict__ w_q,
            const float* __restrict__ bias,
            const float* __restrict__ conv_b) {
    const int blk = blockIdx.x, tid = threadIdx.x;
    if (blk < 64) {
        __shared__ float tile[64][65];
        const int ti = blk >> 3, tj = blk & 7;
#pragma unroll
        for (int q = 0; q < 4; ++q) {
            int idx = q * 256 + tid;
            int r = idx >> 4, c4 = idx & 15;
            float4 v = *(const float4*)(w_v + (size_t)(ti * 64 + r) * DD
                                        + tj * 64 + c4 * 4);
            tile[r][c4 * 4 + 0] = v.x;
            tile[r][c4 * 4 + 1] = v.y;
            tile[r][c4 * 4 + 2] = v.z;
            tile[r][c4 * 4 + 3] = v.w;
        }
        __syncthreads();
#pragma unroll
        for (int q = 0; q < 8; ++q) {
            int slot = q * 256 + tid;
            int nr = slot >> 5, kc = slot & 31;
            __half2 h = __floats2half2_rn(tile[kc * 2][nr],
                                          tile[kc * 2 + 1][nr]);
            *(__half2*)(g_wvt + (size_t)(tj * 64 + nr) * DD + ti * 64 + kc * 2) = h;
        }
    } else {
        const int bb = blk - 64;
        const int ks = bb & 7;
        const int dh = (bb >> 3) & 1;
        const int b  = bb >> 4;
        const int d  = dh * 256 + tid;
        const float* q = query + b * DD + ks * 64;
        const float* w = w_q + (size_t)(ks * 64) * DD + d;
        float a0 = 0.f, a1 = 0.f, a2 = 0.f, a3 = 0.f;
        float a4 = 0.f, a5 = 0.f, a6 = 0.f, a7 = 0.f;
#pragma unroll
        for (int k = 0; k < 64; k += 8) {
            a0 = fmaf(__ldg(q + k),     __ldg(w + (size_t)(k)     * DD), a0);
            a1 = fmaf(__ldg(q + k + 1), __ldg(w + (size_t)(k + 1) * DD), a1);
            a2 = fmaf(__ldg(q + k + 2), __ldg(w + (size_t)(k + 2) * DD), a2);
            a3 = fmaf(__ldg(q + k + 3), __ldg(w + (size_t)(k + 3) * DD), a3);
            a4 = fmaf(__ldg(q + k + 4), __ldg(w + (size_t)(k + 4) * DD), a4);
            a5 = fmaf(__ldg(q + k + 5), __ldg(w + (size_t)(k + 5) * DD), a5);
            a6 = fmaf(__ldg(q + k + 6), __ldg(w + (size_t)(k + 6) * DD), a6);
            a7 = fmaf(__ldg(q + k + 7), __ldg(w + (size_t)(k + 7) * DD), a7);
        }
        float sum = ((a0 + a1) + (a2 + a3)) + ((a4 + a5) + (a6 + a7));
        if (ks == 0) sum += bias[d] + conv_b[d];
        atomicAdd(&g_qw[b * DD + d], sum);
    }
}

// ============================================================================
// scores: block tile M=64 x N=512, K=512. 256 threads / 8 warps, warp tile
// 64x64. A in smem once; per-warp autonomous B pipelines (no block barriers
// in the K loop). fp16 chunk accumulation + fp32 inter-chunk accumulation.
// ============================================================================
__global__ void __launch_bounds__(256, 1)
scores_kernel(const float* __restrict__ value,
              const float* __restrict__ energy,
              const float* __restrict__ conv_w,
              const float* __restrict__ score_w) {
    extern __shared__ char smem[];
    const uint32_t sb = s2u(smem);
    const int tid = threadIdx.x, wid = tid >> 5, lid = tid & 31;
    const int b = blockIdx.x >> 5, tile = blockIdx.x & 31;
    const int s0 = tile * 64;
    const size_t grow0 = (size_t)b * SS + s0;
    const int nwb = wid * 64;

    // ---- per-warp B pipeline: warp w loads its own 64 n-rows, 2-stage ----
    auto cpB = [&](int ch) {
        const int kb = ch * 64;
        const uint32_t bbuf = sb + SM_B
                            + (uint32_t)((wid << 1) + (ch & 1)) * 8192u;
#pragma unroll
        for (int q = 0; q < 16; ++q) {
            int t = lid + q * 32, n = t >> 3, c = t & 7;
            cp16(bbuf + swz((uint32_t)n, (uint32_t)c * 16),
                 g_wvt + (size_t)(nwb + n) * DD + kb + c * 8);
        }
        cp_commit();
    };

    cpB(0);
    cpB(1);

    // ---- epilogue constants ----
    float* c_qwb = (float*)(smem + SM_QWB);
    float* c_cw0 = (float*)(smem + SM_CW0);
    float* c_cw1 = (float*)(smem + SM_CW1);
    float* c_cw2 = (float*)(smem + SM_CW2);
    float* c_sw  = (float*)(smem + SM_SW);
    for (int d = tid; d < DD; d += 256) {
        c_qwb[d] = g_qw[b * DD + d];
        c_cw0[d] = conv_w[d * 3 + 0];
        c_cw1[d] = conv_w[d * 3 + 1];
        c_cw2[d] = conv_w[d * 3 + 2];
        c_sw[d]  = score_w[d];
    }
    if (tid < 64) {
        int s = s0 + tid, gs = b * SS + s;
        ((float*)(smem + SM_E1))[tid] = energy[gs];
        ((float*)(smem + SM_E0))[tid] = (s > 0)      ? energy[gs - 1] : 0.f;
        ((float*)(smem + SM_E2))[tid] = (s < SS - 1) ? energy[gs + 1] : 0.f;
    }

    // ---- A: all 8 chunks (64 x 512 fp32 -> fp16, swizzled 64x64 tiles) ----
#pragma unroll
    for (int ch = 0; ch < 8; ++ch) {
        const int kb = ch * 64;
        char* ah = smem + SM_A + ch * 8192;
#pragma unroll
        for (int q = 0; q < 2; ++q) {
            int t = tid * 2 + q, r = t >> 3, c = t & 7;
            const float4* src =
                (const float4*)(value + (grow0 + r) * DD + kb + c * 8);
            float4 v0 = src[0], v1 = src[1];
            uint4 hh;
            hh.x = packh(__float2half_rn(v0.x), __float2half_rn(v0.y));
            hh.y = packh(__float2half_rn(v0.z), __float2half_rn(v0.w));
            hh.z = packh(__float2half_rn(v1.x), __float2half_rn(v1.y));
            hh.w = packh(__float2half_rn(v1.z), __float2half_rn(v1.w));
            *(uint4*)(ah + swz((uint32_t)r, (uint32_t)c * 16)) = hh;
        }
    }
    __syncthreads();   // the ONLY block barrier before the epilogue

    float acc[4][8][4];
#pragma unroll
    for (int i = 0; i < 4; ++i)
#pragma unroll
        for (int j = 0; j < 8; ++j)
#pragma unroll
            for (int c = 0; c < 4; ++c) acc[i][j][c] = 0.f;

    // compute one K=64 chunk: fp16 accumulation across the 4 k16 steps,
    // then one fp32 add per output. Split into 2 n-halves to bound registers.
    auto compute = [&](int ch) {
        const uint32_t abuf = sb + SM_A + (uint32_t)ch * 8192u;
        const uint32_t bbuf = sb + SM_B
                            + (uint32_t)((wid << 1) + (ch & 1)) * 8192u;
#pragma unroll
        for (int nh = 0; nh < 2; ++nh) {
            uint32_t bfr[4][4][2];   // [s][ni_local][2]
#pragma unroll
            for (int s = 0; s < 4; ++s) {
#pragma unroll
                for (int np = 0; np < 2; ++np) {
                    uint32_t row = nh * 32 + np * 16
                                 + ((lid & 16) >> 1) + (lid & 7);
                    uint32_t col = s * 32 + ((lid & 8) << 1);
                    ldsm4(bfr[s][np * 2][0], bfr[s][np * 2][1],
                          bfr[s][np * 2 + 1][0], bfr[s][np * 2 + 1][1],
                          bbuf + swz(row, col));
                }
            }
#pragma unroll
            for (int mi = 0; mi < 4; ++mi) {
                uint32_t ah[4][4];
#pragma unroll
                for (int s = 0; s < 4; ++s) {
                    uint32_t row = mi * 16 + (lid & 15);
                    uint32_t col = s * 32 + (lid & 16);
                    ldsm4(ah[s][0], ah[s][1], ah[s][2], ah[s][3],
                          abuf + swz(row, col));
                }
#pragma unroll
                for (int nil = 0; nil < 4; ++nil) {
                    uint32_t h0 = 0u, h1 = 0u;   // fp16x2 chunk accumulators
#pragma unroll
                    for (int s = 0; s < 4; ++s)
                        mma16816h(h0, h1, ah[s], bfr[s][nil]);
                    float2 f0 = __half22float2(*reinterpret_cast<__half2*>(&h0));
                    float2 f1 = __half22float2(*reinterpret_cast<__half2*>(&h1));
                    float* a = acc[mi][nh * 4 + nil];
                    a[0] += f0.x;
                    a[1] += f0.y;
                    a[2] += f1.x;
                    a[3] += f1.y;
                }
            }
        }
    };

    // ---- warp-autonomous K loop: no block barriers ----
    for (int ch = 0; ch < 8; ++ch) {
        if (ch < 7) cp_wait1();
        else        cp_wait0();
        __syncwarp();
        compute(ch);
        if (ch < 6) cpB(ch + 2);
    }

    // ---- epilogue ----
    const float* E0 = (const float*)(smem + SM_E0);
    const float* E1 = (const float*)(smem + SM_E1);
    const float* E2 = (const float*)(smem + SM_E2);
    float e0r[8], e1r[8], e2r[8];
#pragma unroll
    for (int mi = 0; mi < 4; ++mi)
#pragma unroll
        for (int h = 0; h < 2; ++h) {
            int r = mi * 16 + h * 8 + (lid >> 2);
            e0r[mi * 2 + h] = E0[r];
            e1r[mi * 2 + h] = E1[r];
            e2r[mi * 2 + h] = E2[r];
        }
    float part[8];
#pragma unroll
    for (int i = 0; i < 8; ++i) part[i] = 0.f;

#pragma unroll
    for (int ni = 0; ni < 8; ++ni) {
        int d0 = nwb + ni * 8 + 2 * (lid & 3);
        float qb0 = c_qwb[d0], qb1 = c_qwb[d0 + 1];
        float w00 = c_cw0[d0], w01 = c_cw0[d0 + 1];
        float w10 = c_cw1[d0], w11 = c_cw1[d0 + 1];
        float w20 = c_cw2[d0], w21 = c_cw2[d0 + 1];
        float sw0 = c_sw[d0],  sw1 = c_sw[d0 + 1];
#pragma unroll
        for (int mi = 0; mi < 4; ++mi)
#pragma unroll
            for (int h = 0; h < 2; ++h) {
                int pi = mi * 2 + h;
                float x0 = acc[mi][ni][h * 2] + qb0
                         + e0r[pi] * w00 + e1r[pi] * w10 + e2r[pi] * w20;
                float x1 = acc[mi][ni][h * 2 + 1] + qb1
                         + e0r[pi] * w01 + e1r[pi] * w11 + e2r[pi] * w21;
                float t0 = 1.f - __fdividef(2.f, __expf(2.f * x0) + 1.f);
                float t1 = 1.f - __fdividef(2.f, __expf(2.f * x1) + 1.f);
                part[pi] = fmaf(t0, sw0, fmaf(t1, sw1, part[pi]));
            }
    }
#pragma unroll
    for (int pi = 0; pi < 8; ++pi) {
        part[pi] += __shfl_xor_sync(0xffffffffu, part[pi], 1);
        part[pi] += __shfl_xor_sync(0xffffffffu, part[pi], 2);
    }
    float* red = (float*)(smem + SM_RED);
    if ((lid & 3) == 0) {
#pragma unroll
        for (int mi = 0; mi < 4; ++mi)
#pragma unroll
            for (int h = 0; h < 2; ++h) {
                int r = mi * 16 + h * 8 + (lid >> 2);
                red[r * 8 + wid] = part[mi * 2 + h];
            }
    }
    __syncthreads();
    if (tid < 64) {
        float sum = 0.f;   // score_b dropped: softmax shift-invariant
#pragma unroll
        for (int w = 0; w < 8; ++w) sum += red[tid * 8 + w];
        g_scores[b * SS + s0 + tid] = sum;
    }
}

// ============================================================================
// softmax per batch -> align  (proven 5us)
// ============================================================================
__global__ void softmax_kernel(float* __restrict__ align_out) {
    __shared__ float wred[8];
    int b = blockIdx.x, t = threadIdx.x, w = t >> 5, l = t & 31;
    const float4* s4 = (const float4*)(g_scores + b * SS);
    float4 v0 = s4[t];
    float4 v1 = s4[t + 256];
    float m = fmaxf(fmaxf(fmaxf(v0.x, v0.y), fmaxf(v0.z, v0.w)),
                    fmaxf(fmaxf(v1.x, v1.y), fmaxf(v1.z, v1.w)));
#pragma unroll
    for (int o = 16; o > 0; o >>= 1)
        m = fmaxf(m, __shfl_xor_sync(0xffffffffu, m, o));
    if (l == 0) wred[w] = m;
    __syncthreads();
    m = wred[0];
#pragma unroll
    for (int i = 1; i < 8; ++i) m = fmaxf(m, wred[i]);
    __syncthreads();

    float4 e0, e1;
    e0.x = __expf(v0.x - m); e0.y = __expf(v0.y - m);
    e0.z = __expf(v0.z - m); e0.w = __expf(v0.w - m);
    e1.x = __expf(v1.x - m); e1.y = __expf(v1.y - m);
    e1.z = __expf(v1.z - m); e1.w = __expf(v1.w - m);
    float sum = e0.x + e0.y + e0.z + e0.w + e1.x + e1.y + e1.z + e1.w;
#pragma unroll
    for (int o = 16; o > 0; o >>= 1)
        sum += __shfl_xor_sync(0xffffffffu, sum, o);
    if (l == 0) wred[w] = sum;
    __syncthreads();
    sum = wred[0];
#pragma unroll
    for (int i = 1; i < 8; ++i) sum += wred[i];
    float inv = 1.f / sum;
    e0.x *= inv; e0.y *= inv; e0.z *= inv; e0.w *= inv;
    e1.x *= inv; e1.y *= inv; e1.z *= inv; e1.w *= inv;
    float4* a4 = (float4*)(align_out + b * SS);
    a4[t] = e0;
    a4[t + 256] = e1;
}

// ============================================================================
// context: ctx[b,d] = sum_s align[b,s] * value[b,s,d]   (R4-proven)
// ============================================================================
__global__ void context_kernel(const float* __restrict__ value,
                               const float* __restrict__ align,
                               float* __restrict__ ctx) {
    int b = blockIdx.x, dch = blockIdx.y, sch = blockIdx.z;
    int d = dch * 128 + threadIdx.x;
    const float* vb = value + ((size_t)b * SS + sch * 256) * DD + d;
    const float* ab = align + b * SS + sch * 256;
    float acc = 0.f;
#pragma unroll 8
    for (int s = 0; s < 256; ++s)
        acc = fmaf(ab[s], vb[(size_t)s * DD], acc);
    atomicAdd(&ctx[b * DD + d], acc);
}

// ============================================================================
// launch
// ============================================================================
extern "C" void kernel_launch(void* const* d_in, const int* in_sizes, int n_in,
                              void* d_out, int out_size) {
    const float* query   = (const float*)d_in[0];
    const float* value   = (const float*)d_in[1];
    const float* energy  = (const float*)d_in[2];
    const float* conv_w  = (const float*)d_in[3];
    const float* conv_b  = (const float*)d_in[4];
    const float* w_q     = (const float*)d_in[5];
    const float* w_v     = (const float*)d_in[6];
    const float* bias    = (const float*)d_in[7];
    const float* score_w = (const float*)d_in[8];
    float* out_ctx   = (float*)d_out;            // [B*D]
    float* out_align = (float*)d_out + BB * DD;  // [B*S]

    cudaFuncSetAttribute(scores_kernel,
                         cudaFuncAttributeMaxDynamicSharedMemorySize, SM_TOT);

    zero_kernel<<<(BB * DD + 255) / 256, 256>>>(out_ctx);
    prep_kernel<<<576, 256>>>(w_v, query, w_q, bias, conv_b);
    scores_kernel<<<BB * 32, 256, SM_TOT>>>(value, energy, conv_w, score_w);
    softmax_kernel<<<BB, 256>>>(out_align);
    context_kernel<<<dim3(BB, DD / 128, SS / 256), 128>>>(value, out_align,
                                                          out_ctx);
}

// round 12
// speedup vs baseline: 1.2968x; 1.2968x over previous
#include <cuda_runtime.h>
#include <cuda_fp16.h>
#include <cstdint>

// ============================================================================
// LocationAwareAttention  B=32, S=2048, D=512   (family-common PTX only:
// mma.sync + ldmatrix + cp.async — NO tcgen05, target is sm_103)
//
// R12: f32-accumulator mma restored (R11 falsified fp16-acc 2x rate).
// 16 autonomous warps / 512 threads (4 independent pipelines per SMSP vs
// R10's 2), warp tile 32x64. B rings pair-shared per n-group: each warp of an
// (mg0,mg1) pair cp.asyncs half the stage, waits its own group, then a named
// pair barrier (bar.sync 1+ng, 64). No block-wide barriers in the K loop.
// Periphery = R9-proven.
// Output: d_out = [ctx (B*D) | align (B*S)] fp32
// ============================================================================

#define BB 32
#define SS 2048
#define DD 512

__device__ __half g_wvt[DD * DD];     // w_v^T [n][k] fp16
__device__ float  g_qw[BB * DD];      // q@w_q + bias + conv_b  (atomic-built)
__device__ float  g_scores[BB * SS];

// ---------------- SMEM layout (bytes) ----------------
#define SM_A    0                      // 8 chunks x (64x64 fp16, swizzled) = 64KB
#define SM_B    65536                  // 8 ngroups x 2 stages x 8KB = 128KB
#define SM_QWB  196608
#define SM_CW0  198656
#define SM_CW1  200704
#define SM_CW2  202752
#define SM_SW   204800
#define SM_E0   206848
#define SM_E1   207104
#define SM_E2   207360
#define SM_RED  207616                 // 64 x 8 f32
#define SM_TOT  209664

// ---------------- PTX helpers ----------------
__device__ __forceinline__ uint32_t s2u(const void* p) {
    uint32_t a;
    asm("{ .reg .u64 t; cvta.to.shared.u64 t, %1; cvt.u32.u64 %0, t; }"
        : "=r"(a) : "l"(p));
    return a;
}
__device__ __forceinline__ void cp16(uint32_t dst, const void* src) {
    asm volatile("cp.async.ca.shared.global [%0], [%1], 16;"
                 :: "r"(dst), "l"(src) : "memory");
}
__device__ __forceinline__ void cp_commit() {
    asm volatile("cp.async.commit_group;" ::: "memory");
}
__device__ __forceinline__ void cp_wait0() {
    asm volatile("cp.async.wait_group 0;" ::: "memory");
}
__device__ __forceinline__ void cp_wait1() {
    asm volatile("cp.async.wait_group 1;" ::: "memory");
}
// pair barrier: 2 warps (64 threads), named barrier id in [1,8]
__device__ __forceinline__ void barp(int id) {
    asm volatile("bar.sync %0, 64;" :: "r"(id) : "memory");
}
__device__ __forceinline__ void ldsm4(uint32_t& r0, uint32_t& r1,
                                      uint32_t& r2, uint32_t& r3, uint32_t a) {
    asm volatile("ldmatrix.sync.aligned.m8n8.x4.shared.b16 {%0,%1,%2,%3}, [%4];"
                 : "=r"(r0), "=r"(r1), "=r"(r2), "=r"(r3) : "r"(a));
}
__device__ __forceinline__ void mma16816(float* d, const uint32_t* a,
                                         const uint32_t* b) {
    asm volatile(
        "mma.sync.aligned.m16n8k16.row.col.f32.f16.f16.f32 "
        "{%0,%1,%2,%3}, {%4,%5,%6,%7}, {%8,%9}, {%0,%1,%2,%3};"
        : "+f"(d[0]), "+f"(d[1]), "+f"(d[2]), "+f"(d[3])
        : "r"(a[0]), "r"(a[1]), "r"(a[2]), "r"(a[3]), "r"(b[0]), "r"(b[1]));
}
__device__ __forceinline__ uint32_t packh(__half a, __half b) {
    __half2 h2; h2.x = a; h2.y = b;
    return *(uint32_t*)&h2;
}
__device__ __forceinline__ uint32_t swz(uint32_t row, uint32_t colByte) {
    return row * 128u + (colByte ^ ((row & 7u) << 4));
}

// ============================================================================
// zero: g_qw and ctx (both BB*DD) — must precede prep's atomics.
// ============================================================================
__global__ void zero_kernel(float* __restrict__ ctx) {
    int i = blockIdx.x * blockDim.x + threadIdx.x;
    if (i < BB * DD) { ctx[i] = 0.f; g_qw[i] = 0.f; }
}

// ============================================================================
// prep (R9-proven): 576 blocks x 256 threads.
// ============================================================================
__global__ void __launch_bounds__(256)
prep_kernel(const float* __restrict__ w_v,
            const float* __restrict__ query,
            const float* __restrict__ w_q,
            const float* __restrict__ bias,
            const float* __restrict__ conv_b) {
    const int blk = blockIdx.x, tid = threadIdx.x;
    if (blk < 64) {
        __shared__ float tile[64][65];
        const int ti = blk >> 3, tj = blk & 7;
#pragma unroll
        for (int q = 0; q < 4; ++q) {
            int idx = q * 256 + tid;
            int r = idx >> 4, c4 = idx & 15;
            float4 v = *(const float4*)(w_v + (size_t)(ti * 64 + r) * DD
                                        + tj * 64 + c4 * 4);
            tile[r][c4 * 4 + 0] = v.x;
            tile[r][c4 * 4 + 1] = v.y;
            tile[r][c4 * 4 + 2] = v.z;
            tile[r][c4 * 4 + 3] = v.w;
        }
        __syncthreads();
#pragma unroll
        for (int q = 0; q < 8; ++q) {
            int slot = q * 256 + tid;
            int nr = slot >> 5, kc = slot & 31;
            __half2 h = __floats2half2_rn(tile[kc * 2][nr],
                                          tile[kc * 2 + 1][nr]);
            *(__half2*)(g_wvt + (size_t)(tj * 64 + nr) * DD + ti * 64 + kc * 2) = h;
        }
    } else {
        const int bb = blk - 64;
        const int ks = bb & 7;
        const int dh = (bb >> 3) & 1;
        const int b  = bb >> 4;
        const int d  = dh * 256 + tid;
        const float* q = query + b * DD + ks * 64;
        const float* w = w_q + (size_t)(ks * 64) * DD + d;
        float a0 = 0.f, a1 = 0.f, a2 = 0.f, a3 = 0.f;
        float a4 = 0.f, a5 = 0.f, a6 = 0.f, a7 = 0.f;
#pragma unroll
        for (int k = 0; k < 64; k += 8) {
            a0 = fmaf(__ldg(q + k),     __ldg(w + (size_t)(k)     * DD), a0);
            a1 = fmaf(__ldg(q + k + 1), __ldg(w + (size_t)(k + 1) * DD), a1);
            a2 = fmaf(__ldg(q + k + 2), __ldg(w + (size_t)(k + 2) * DD), a2);
            a3 = fmaf(__ldg(q + k + 3), __ldg(w + (size_t)(k + 3) * DD), a3);
            a4 = fmaf(__ldg(q + k + 4), __ldg(w + (size_t)(k + 4) * DD), a4);
            a5 = fmaf(__ldg(q + k + 5), __ldg(w + (size_t)(k + 5) * DD), a5);
            a6 = fmaf(__ldg(q + k + 6), __ldg(w + (size_t)(k + 6) * DD), a6);
            a7 = fmaf(__ldg(q + k + 7), __ldg(w + (size_t)(k + 7) * DD), a7);
        }
        float sum = ((a0 + a1) + (a2 + a3)) + ((a4 + a5) + (a6 + a7));
        if (ks == 0) sum += bias[d] + conv_b[d];
        atomicAdd(&g_qw[b * DD + d], sum);
    }
}

// ============================================================================
// scores: block tile M=64 x N=512, K=512. 512 threads / 16 warps, warp tile
// 32x64 (mg=wid>>3 m-half, ng=wid&7 n-group). A in smem once; pair-shared
// autonomous B pipelines; named pair barriers only.
// ============================================================================
__global__ void __launch_bounds__(512, 1)
scores_kernel(const float* __restrict__ value,
              const float* __restrict__ energy,
              const float* __restrict__ conv_w,
              const float* __restrict__ score_w) {
    extern __shared__ char smem[];
    const uint32_t sb = s2u(smem);
    const int tid = threadIdx.x, wid = tid >> 5, lid = tid & 31;
    const int mg = wid >> 3;           // 0..1 : m rows [mg*32, +32)
    const int ng = wid & 7;            // 0..7 : n cols [ng*64, +64)
    const int b = blockIdx.x >> 5, tile = blockIdx.x & 31;
    const int s0 = tile * 64;
    const size_t grow0 = (size_t)b * SS + s0;
    const int nwb = ng * 64;
    const int mwb = mg * 32;
    const int barid = 1 + ng;

    // ---- pair-shared B ring: warp loads its mg-half of the 64 n-rows ----
    auto cpB = [&](int ch) {
        const int kb = ch * 64;
        const uint32_t bbuf = sb + SM_B
                            + (uint32_t)((ng << 1) + (ch & 1)) * 8192u;
#pragma unroll
        for (int q = 0; q < 8; ++q) {
            int t = lid + q * 32;
            int n = mg * 32 + (t >> 3), c = t & 7;
            cp16(bbuf + swz((uint32_t)n, (uint32_t)c * 16),
                 g_wvt + (size_t)(nwb + n) * DD + kb + c * 8);
        }
        cp_commit();
    };

    cpB(0);
    cpB(1);

    // ---- epilogue constants ----
    float* c_qwb = (float*)(smem + SM_QWB);
    float* c_cw0 = (float*)(smem + SM_CW0);
    float* c_cw1 = (float*)(smem + SM_CW1);
    float* c_cw2 = (float*)(smem + SM_CW2);
    float* c_sw  = (float*)(smem + SM_SW);
    if (tid < DD) {
        int d = tid;
        c_qwb[d] = g_qw[b * DD + d];
        c_cw0[d] = conv_w[d * 3 + 0];
        c_cw1[d] = conv_w[d * 3 + 1];
        c_cw2[d] = conv_w[d * 3 + 2];
        c_sw[d]  = score_w[d];
    }
    if (tid < 64) {
        int s = s0 + tid, gs = b * SS + s;
        ((float*)(smem + SM_E1))[tid] = energy[gs];
        ((float*)(smem + SM_E0))[tid] = (s > 0)      ? energy[gs - 1] : 0.f;
        ((float*)(smem + SM_E2))[tid] = (s < SS - 1) ? energy[gs + 1] : 0.f;
    }

    // ---- A: all 8 chunks (64 x 512 fp32 -> fp16, swizzled 64x64 tiles) ----
#pragma unroll
    for (int ch = 0; ch < 8; ++ch) {
        const int kb = ch * 64;
        char* ah = smem + SM_A + ch * 8192;
        int r = tid >> 3, c = tid & 7;
        const float4* src = (const float4*)(value + (grow0 + r) * DD + kb + c * 8);
        float4 v0 = src[0], v1 = src[1];
        uint4 hh;
        hh.x = packh(__float2half_rn(v0.x), __float2half_rn(v0.y));
        hh.y = packh(__float2half_rn(v0.z), __float2half_rn(v0.w));
        hh.z = packh(__float2half_rn(v1.x), __float2half_rn(v1.y));
        hh.w = packh(__float2half_rn(v1.z), __float2half_rn(v1.w));
        *(uint4*)(ah + swz((uint32_t)r, (uint32_t)c * 16)) = hh;
    }
    __syncthreads();   // the ONLY block barrier before the epilogue

    float acc[2][8][4];
#pragma unroll
    for (int i = 0; i < 2; ++i)
#pragma unroll
        for (int j = 0; j < 8; ++j)
#pragma unroll
            for (int c = 0; c < 4; ++c) acc[i][j][c] = 0.f;

    auto compute = [&](int ch) {
        const uint32_t abuf = sb + SM_A + (uint32_t)ch * 8192u;
        const uint32_t bbuf = sb + SM_B
                            + (uint32_t)((ng << 1) + (ch & 1)) * 8192u;
#pragma unroll
        for (int s = 0; s < 4; ++s) {
            uint32_t bfr[8][2];
#pragma unroll
            for (int np = 0; np < 4; ++np) {
                uint32_t row = np * 16 + ((lid & 16) >> 1) + (lid & 7);
                uint32_t col = s * 32 + ((lid & 8) << 1);
                ldsm4(bfr[np * 2][0], bfr[np * 2][1],
                      bfr[np * 2 + 1][0], bfr[np * 2 + 1][1],
                      bbuf + swz(row, col));
            }
#pragma unroll
            for (int mi = 0; mi < 2; ++mi) {
                uint32_t row = mwb + mi * 16 + (lid & 15);
                uint32_t col = s * 32 + (lid & 16);
                uint32_t ah[4];
                ldsm4(ah[0], ah[1], ah[2], ah[3], abuf + swz(row, col));
#pragma unroll
                for (int ni = 0; ni < 8; ++ni)
                    mma16816(acc[mi][ni], ah, bfr[ni]);
            }
        }
    };

    // ---- pair-autonomous K loop: named pair barriers only ----
    for (int ch = 0; ch < 8; ++ch) {
        if (ch < 7) cp_wait1();   // this warp's half of stage(ch) arrived
        else        cp_wait0();
        barp(barid);              // partner's half visible too
        compute(ch);
        barp(barid);              // pair done reading stage ch&1
        if (ch < 6) cpB(ch + 2);  // refill the just-freed stage
    }

    // ---- epilogue ----
    const float* E0 = (const float*)(smem + SM_E0);
    const float* E1 = (const float*)(smem + SM_E1);
    const float* E2 = (const float*)(smem + SM_E2);
    float e0r[4], e1r[4], e2r[4];
#pragma unroll
    for (int mi = 0; mi < 2; ++mi)
#pragma unroll
        for (int h = 0; h < 2; ++h) {
            int r = mwb + mi * 16 + h * 8 + (lid >> 2);
            e0r[mi * 2 + h] = E0[r];
            e1r[mi * 2 + h] = E1[r];
            e2r[mi * 2 + h] = E2[r];
        }
    float part[4];
#pragma unroll
    for (int i = 0; i < 4; ++i) part[i] = 0.f;

#pragma unroll
    for (int ni = 0; ni < 8; ++ni) {
        int d0 = nwb + ni * 8 + 2 * (lid & 3);
        float qb0 = c_qwb[d0], qb1 = c_qwb[d0 + 1];
        float w00 = c_cw0[d0], w01 = c_cw0[d0 + 1];
        float w10 = c_cw1[d0], w11 = c_cw1[d0 + 1];
        float w20 = c_cw2[d0], w21 = c_cw2[d0 + 1];
        float sw0 = c_sw[d0],  sw1 = c_sw[d0 + 1];
#pragma unroll
        for (int mi = 0; mi < 2; ++mi)
#pragma unroll
            for (int h = 0; h < 2; ++h) {
                int pi = mi * 2 + h;
                float x0 = acc[mi][ni][h * 2] + qb0
                         + e0r[pi] * w00 + e1r[pi] * w10 + e2r[pi] * w20;
                float x1 = acc[mi][ni][h * 2 + 1] + qb1
                         + e0r[pi] * w01 + e1r[pi] * w11 + e2r[pi] * w21;
                float t0 = 1.f - __fdividef(2.f, __expf(2.f * x0) + 1.f);
                float t1 = 1.f - __fdividef(2.f, __expf(2.f * x1) + 1.f);
                part[pi] = fmaf(t0, sw0, fmaf(t1, sw1, part[pi]));
            }
    }
#pragma unroll
    for (int pi = 0; pi < 4; ++pi) {
        part[pi] += __shfl_xor_sync(0xffffffffu, part[pi], 1);
        part[pi] += __shfl_xor_sync(0xffffffffu, part[pi], 2);
    }
    float* red = (float*)(smem + SM_RED);
    if ((lid & 3) == 0) {
#pragma unroll
        for (int mi = 0; mi < 2; ++mi)
#pragma unroll
            for (int h = 0; h < 2; ++h) {
                int r = mwb + mi * 16 + h * 8 + (lid >> 2);
                red[r * 8 + ng] = part[mi * 2 + h];
            }
    }
    __syncthreads();
    if (tid < 64) {
        float sum = 0.f;   // score_b dropped: softmax shift-invariant
#pragma unroll
        for (int w = 0; w < 8; ++w) sum += red[tid * 8 + w];
        g_scores[b * SS + s0 + tid] = sum;
    }
}

// ============================================================================
// softmax per batch -> align  (proven 5us)
// ============================================================================
__global__ void softmax_kernel(float* __restrict__ align_out) {
    __shared__ float wred[8];
    int b = blockIdx.x, t = threadIdx.x, w = t >> 5, l = t & 31;
    const float4* s4 = (const float4*)(g_scores + b * SS);
    float4 v0 = s4[t];
    float4 v1 = s4[t + 256];
    float m = fmaxf(fmaxf(fmaxf(v0.x, v0.y), fmaxf(v0.z, v0.w)),
                    fmaxf(fmaxf(v1.x, v1.y), fmaxf(v1.z, v1.w)));
#pragma unroll
    for (int o = 16; o > 0; o >>= 1)
        m = fmaxf(m, __shfl_xor_sync(0xffffffffu, m, o));
    if (l == 0) wred[w] = m;
    __syncthreads();
    m = wred[0];
#pragma unroll
    for (int i = 1; i < 8; ++i) m = fmaxf(m, wred[i]);
    __syncthreads();

    float4 e0, e1;
    e0.x = __expf(v0.x - m); e0.y = __expf(v0.y - m);
    e0.z = __expf(v0.z - m); e0.w = __expf(v0.w - m);
    e1.x = __expf(v1.x - m); e1.y = __expf(v1.y - m);
    e1.z = __expf(v1.z - m); e1.w = __expf(v1.w - m);
    float sum = e0.x + e0.y + e0.z + e0.w + e1.x + e1.y + e1.z + e1.w;
#pragma unroll
    for (int o = 16; o > 0; o >>= 1)
        sum += __shfl_xor_sync(0xffffffffu, sum, o);
    if (l == 0) wred[w] = sum;
    __syncthreads();
    sum = wred[0];
#pragma unroll
    for (int i = 1; i < 8; ++i) sum += wred[i];
    float inv = 1.f / sum;
    e0.x *= inv; e0.y *= inv; e0.z *= inv; e0.w *= inv;
    e1.x *= inv; e1.y *= inv; e1.z *= inv; e1.w *= inv;
    float4* a4 = (float4*)(align_out + b * SS);
    a4[t] = e0;
    a4[t + 256] = e1;
}

// ============================================================================
// context: ctx[b,d] = sum_s align[b,s] * value[b,s,d]   (R4-proven)
// ============================================================================
__global__ void context_kernel(const float* __restrict__ value,
                               const float* __restrict__ align,
                               float* __restrict__ ctx) {
    int b = blockIdx.x, dch = blockIdx.y, sch = blockIdx.z;
    int d = dch * 128 + threadIdx.x;
    const float* vb = value + ((size_t)b * SS + sch * 256) * DD + d;
    const float* ab = align + b * SS + sch * 256;
    float acc = 0.f;
#pragma unroll 8
    for (int s = 0; s < 256; ++s)
        acc = fmaf(ab[s], vb[(size_t)s * DD], acc);
    atomicAdd(&ctx[b * DD + d], acc);
}

// ============================================================================
// launch
// ============================================================================
extern "C" void kernel_launch(void* const* d_in, const int* in_sizes, int n_in,
                              void* d_out, int out_size) {
    const float* query   = (const float*)d_in[0];
    const float* value   = (const float*)d_in[1];
    const float* energy  = (const float*)d_in[2];
    const float* conv_w  = (const float*)d_in[3];
    const float* conv_b  = (const float*)d_in[4];
    const float* w_q     = (const float*)d_in[5];
    const float* w_v     = (const float*)d_in[6];
    const float* bias    = (const float*)d_in[7];
    const float* score_w = (const float*)d_in[8];
    float* out_ctx   = (float*)d_out;            // [B*D]
    float* out_align = (float*)d_out + BB * DD;  // [B*S]

    cudaFuncSetAttribute(scores_kernel,
                         cudaFuncAttributeMaxDynamicSharedMemorySize, SM_TOT);

    zero_kernel<<<(BB * DD + 255) / 256, 256>>>(out_ctx);
    prep_kernel<<<576, 256>>>(w_v, query, w_q, bias, conv_b);
    scores_kernel<<<BB * 32, 512, SM_TOT>>>(value, energy, conv_w, score_w);
    softmax_kernel<<<BB, 256>>>(out_align);
    context_kernel<<<dim3(BB, DD / 128, SS / 256), 128>>>(value, out_align,
                                                          out_ctx);
}

// round 13
// speedup vs baseline: 1.4193x; 1.0944x over previous
#include <cuda_runtime.h>
#include <cuda_fp16.h>
#include <cstdint>

// ============================================================================
// LocationAwareAttention  B=32, S=2048, D=512   (family-common PTX only:
// mma.sync + ldmatrix + cp.async — NO tcgen05, target is sm_103)
//
// R13: consolidation on R10 (best measured scores config; R11/R12 falsified
// fp16-acc rate and 4-pipeline scheduling). Deltas:
//  - tanh.approx.f32 in the epilogue (1 MUFU vs 2) ~3-4us
//  - zero_kernel removed: qw built race-free into g_qw_part[8] slices
//    (scores sums parts), ctx zeroed inside softmax. 4 launches total.
// Output: d_out = [ctx (B*D) | align (B*S)] fp32
// ============================================================================

#define BB 32
#define SS 2048
#define DD 512

__device__ __half g_wvt[DD * DD];          // w_v^T [n][k] fp16
__device__ float  g_qw_part[8 * BB * DD];  // k-split partials of q@w_q(+bias)
__device__ float  g_scores[BB * SS];

// ---------------- SMEM layout (bytes) ----------------
#define SM_A    0                      // 8 chunks x (64x64 fp16, swizzled) = 64KB
#define SM_B    65536                  // 8 warps x 2 stages x 8KB = 128KB
#define SM_QWB  196608
#define SM_CW0  198656
#define SM_CW1  200704
#define SM_CW2  202752
#define SM_SW   204800
#define SM_E0   206848
#define SM_E1   207104
#define SM_E2   207360
#define SM_RED  207616                 // 64 x 8 f32
#define SM_TOT  209664

// ---------------- PTX helpers ----------------
__device__ __forceinline__ uint32_t s2u(const void* p) {
    uint32_t a;
    asm("{ .reg .u64 t; cvta.to.shared.u64 t, %1; cvt.u32.u64 %0, t; }"
        : "=r"(a) : "l"(p));
    return a;
}
__device__ __forceinline__ void cp16(uint32_t dst, const void* src) {
    asm volatile("cp.async.ca.shared.global [%0], [%1], 16;"
                 :: "r"(dst), "l"(src) : "memory");
}
__device__ __forceinline__ void cp_commit() {
    asm volatile("cp.async.commit_group;" ::: "memory");
}
__device__ __forceinline__ void cp_wait0() {
    asm volatile("cp.async.wait_group 0;" ::: "memory");
}
__device__ __forceinline__ void cp_wait1() {
    asm volatile("cp.async.wait_group 1;" ::: "memory");
}
__device__ __forceinline__ void ldsm4(uint32_t& r0, uint32_t& r1,
                                      uint32_t& r2, uint32_t& r3, uint32_t a) {
    asm volatile("ldmatrix.sync.aligned.m8n8.x4.shared.b16 {%0,%1,%2,%3}, [%4];"
                 : "=r"(r0), "=r"(r1), "=r"(r2), "=r"(r3) : "r"(a));
}
__device__ __forceinline__ void mma16816(float* d, const uint32_t* a,
                                         const uint32_t* b) {
    asm volatile(
        "mma.sync.aligned.m16n8k16.row.col.f32.f16.f16.f32 "
        "{%0,%1,%2,%3}, {%4,%5,%6,%7}, {%8,%9}, {%0,%1,%2,%3};"
        : "+f"(d[0]), "+f"(d[1]), "+f"(d[2]), "+f"(d[3])
        : "r"(a[0]), "r"(a[1]), "r"(a[2]), "r"(a[3]), "r"(b[0]), "r"(b[1]));
}
__device__ __forceinline__ float tanh_fast(float x) {
    float y;
    asm("tanh.approx.f32 %0, %1;" : "=f"(y) : "f"(x));
    return y;
}
__device__ __forceinline__ uint32_t packh(__half a, __half b) {
    __half2 h2; h2.x = a; h2.y = b;
    return *(uint32_t*)&h2;
}
__device__ __forceinline__ uint32_t swz(uint32_t row, uint32_t colByte) {
    return row * 128u + (colByte ^ ((row & 7u) << 4));
}

// ============================================================================
// prep: 576 blocks x 256 threads.
//   [0,64):   w_v^T -> fp16 coalesced 64x64 smem-tile transpose
//   [64,576): qw k-split: block (b, dh, ks) writes g_qw_part[ks][b][d]
//             (disjoint -> no atomics, no zeroing)
// ============================================================================
__global__ void __launch_bounds__(256)
prep_kernel(const float* __restrict__ w_v,
            const float* __restrict__ query,
            const float* __restrict__ w_q,
            const float* __restrict__ bias,
            const float* __restrict__ conv_b) {
    const int blk = blockIdx.x, tid = threadIdx.x;
    if (blk < 64) {
        __shared__ float tile[64][65];
        const int ti = blk >> 3, tj = blk & 7;
#pragma unroll
        for (int q = 0; q < 4; ++q) {
            int idx = q * 256 + tid;
            int r = idx >> 4, c4 = idx & 15;
            float4 v = *(const float4*)(w_v + (size_t)(ti * 64 + r) * DD
                                        + tj * 64 + c4 * 4);
            tile[r][c4 * 4 + 0] = v.x;
            tile[r][c4 * 4 + 1] = v.y;
            tile[r][c4 * 4 + 2] = v.z;
            tile[r][c4 * 4 + 3] = v.w;
        }
        __syncthreads();
#pragma unroll
        for (int q = 0; q < 8; ++q) {
            int slot = q * 256 + tid;
            int nr = slot >> 5, kc = slot & 31;
            __half2 h = __floats2half2_rn(tile[kc * 2][nr],
                                          tile[kc * 2 + 1][nr]);
            *(__half2*)(g_wvt + (size_t)(tj * 64 + nr) * DD + ti * 64 + kc * 2) = h;
        }
    } else {
        const int bb = blk - 64;
        const int ks = bb & 7;
        const int dh = (bb >> 3) & 1;
        const int b  = bb >> 4;
        const int d  = dh * 256 + tid;
        const float* q = query + b * DD + ks * 64;
        const float* w = w_q + (size_t)(ks * 64) * DD + d;
        float a0 = 0.f, a1 = 0.f, a2 = 0.f, a3 = 0.f;
        float a4 = 0.f, a5 = 0.f, a6 = 0.f, a7 = 0.f;
#pragma unroll
        for (int k = 0; k < 64; k += 8) {
            a0 = fmaf(__ldg(q + k),     __ldg(w + (size_t)(k)     * DD), a0);
            a1 = fmaf(__ldg(q + k + 1), __ldg(w + (size_t)(k + 1) * DD), a1);
            a2 = fmaf(__ldg(q + k + 2), __ldg(w + (size_t)(k + 2) * DD), a2);
            a3 = fmaf(__ldg(q + k + 3), __ldg(w + (size_t)(k + 3) * DD), a3);
            a4 = fmaf(__ldg(q + k + 4), __ldg(w + (size_t)(k + 4) * DD), a4);
            a5 = fmaf(__ldg(q + k + 5), __ldg(w + (size_t)(k + 5) * DD), a5);
            a6 = fmaf(__ldg(q + k + 6), __ldg(w + (size_t)(k + 6) * DD), a6);
            a7 = fmaf(__ldg(q + k + 7), __ldg(w + (size_t)(k + 7) * DD), a7);
        }
        float sum = ((a0 + a1) + (a2 + a3)) + ((a4 + a5) + (a6 + a7));
        if (ks == 0) sum += bias[d] + conv_b[d];
        g_qw_part[(ks * BB + b) * DD + d] = sum;
    }
}

// ============================================================================
// scores: block tile M=64 x N=512, K=512. 256 threads / 8 warps, warp tile
// 64x64. A in smem once; per-warp autonomous B pipelines (no block barriers
// in the K loop). R10-proven GEMM core.
// ============================================================================
__global__ void __launch_bounds__(256, 1)
scores_kernel(const float* __restrict__ value,
              const float* __restrict__ energy,
              const float* __restrict__ conv_w,
              const float* __restrict__ score_w) {
    extern __shared__ char smem[];
    const uint32_t sb = s2u(smem);
    const int tid = threadIdx.x, wid = tid >> 5, lid = tid & 31;
    const int b = blockIdx.x >> 5, tile = blockIdx.x & 31;
    const int s0 = tile * 64;
    const size_t grow0 = (size_t)b * SS + s0;
    const int nwb = wid * 64;

    // ---- per-warp B pipeline: warp w loads its own 64 n-rows, 2-stage ----
    auto cpB = [&](int ch) {
        const int kb = ch * 64;
        const uint32_t bbuf = sb + SM_B
                            + (uint32_t)((wid << 1) + (ch & 1)) * 8192u;
#pragma unroll
        for (int q = 0; q < 16; ++q) {
            int t = lid + q * 32, n = t >> 3, c = t & 7;
            cp16(bbuf + swz((uint32_t)n, (uint32_t)c * 16),
                 g_wvt + (size_t)(nwb + n) * DD + kb + c * 8);
        }
        cp_commit();
    };

    cpB(0);
    cpB(1);

    // ---- epilogue constants (qw = sum of 8 k-split parts) ----
    float* c_qwb = (float*)(smem + SM_QWB);
    float* c_cw0 = (float*)(smem + SM_CW0);
    float* c_cw1 = (float*)(smem + SM_CW1);
    float* c_cw2 = (float*)(smem + SM_CW2);
    float* c_sw  = (float*)(smem + SM_SW);
    for (int d = tid; d < DD; d += 256) {
        float qsum = 0.f;
#pragma unroll
        for (int ks = 0; ks < 8; ++ks)
            qsum += g_qw_part[(ks * BB + b) * DD + d];
        c_qwb[d] = qsum;
        c_cw0[d] = conv_w[d * 3 + 0];
        c_cw1[d] = conv_w[d * 3 + 1];
        c_cw2[d] = conv_w[d * 3 + 2];
        c_sw[d]  = score_w[d];
    }
    if (tid < 64) {
        int s = s0 + tid, gs = b * SS + s;
        ((float*)(smem + SM_E1))[tid] = energy[gs];
        ((float*)(smem + SM_E0))[tid] = (s > 0)      ? energy[gs - 1] : 0.f;
        ((float*)(smem + SM_E2))[tid] = (s < SS - 1) ? energy[gs + 1] : 0.f;
    }

    // ---- A: all 8 chunks (64 x 512 fp32 -> fp16, swizzled 64x64 tiles) ----
#pragma unroll
    for (int ch = 0; ch < 8; ++ch) {
        const int kb = ch * 64;
        char* ah = smem + SM_A + ch * 8192;
#pragma unroll
        for (int q = 0; q < 2; ++q) {
            int t = tid * 2 + q, r = t >> 3, c = t & 7;
            const float4* src =
                (const float4*)(value + (grow0 + r) * DD + kb + c * 8);
            float4 v0 = src[0], v1 = src[1];
            uint4 hh;
            hh.x = packh(__float2half_rn(v0.x), __float2half_rn(v0.y));
            hh.y = packh(__float2half_rn(v0.z), __float2half_rn(v0.w));
            hh.z = packh(__float2half_rn(v1.x), __float2half_rn(v1.y));
            hh.w = packh(__float2half_rn(v1.z), __float2half_rn(v1.w));
            *(uint4*)(ah + swz((uint32_t)r, (uint32_t)c * 16)) = hh;
        }
    }
    __syncthreads();   // the ONLY block barrier before the epilogue

    float acc[4][8][4];
#pragma unroll
    for (int i = 0; i < 4; ++i)
#pragma unroll
        for (int j = 0; j < 8; ++j)
#pragma unroll
            for (int c = 0; c < 4; ++c) acc[i][j][c] = 0.f;

    auto compute = [&](int ch) {
        const uint32_t abuf = sb + SM_A + (uint32_t)ch * 8192u;
        const uint32_t bbuf = sb + SM_B
                            + (uint32_t)((wid << 1) + (ch & 1)) * 8192u;
#pragma unroll
        for (int s = 0; s < 4; ++s) {
            uint32_t bfr[8][2];
#pragma unroll
            for (int np = 0; np < 4; ++np) {
                uint32_t row = np * 16 + ((lid & 16) >> 1) + (lid & 7);
                uint32_t col = s * 32 + ((lid & 8) << 1);
                ldsm4(bfr[np * 2][0], bfr[np * 2][1],
                      bfr[np * 2 + 1][0], bfr[np * 2 + 1][1],
                      bbuf + swz(row, col));
            }
#pragma unroll
            for (int mi = 0; mi < 4; ++mi) {
                uint32_t row = mi * 16 + (lid & 15);
                uint32_t col = s * 32 + (lid & 16);
                uint32_t ah[4];
                ldsm4(ah[0], ah[1], ah[2], ah[3], abuf + swz(row, col));
#pragma unroll
                for (int ni = 0; ni < 8; ++ni)
                    mma16816(acc[mi][ni], ah, bfr[ni]);
            }
        }
    };

    // ---- warp-autonomous K loop: no block barriers ----
    for (int ch = 0; ch < 8; ++ch) {
        if (ch < 7) cp_wait1();
        else        cp_wait0();
        __syncwarp();
        compute(ch);
        if (ch < 6) cpB(ch + 2);
    }

    // ---- epilogue: x = acc + qw + conv(e); score += tanh.approx(x)*sw ----
    const float* E0 = (const float*)(smem + SM_E0);
    const float* E1 = (const float*)(smem + SM_E1);
    const float* E2 = (const float*)(smem + SM_E2);
    float e0r[8], e1r[8], e2r[8];
#pragma unroll
    for (int mi = 0; mi < 4; ++mi)
#pragma unroll
        for (int h = 0; h < 2; ++h) {
            int r = mi * 16 + h * 8 + (lid >> 2);
            e0r[mi * 2 + h] = E0[r];
            e1r[mi * 2 + h] = E1[r];
            e2r[mi * 2 + h] = E2[r];
        }
    float part[8];
#pragma unroll
    for (int i = 0; i < 8; ++i) part[i] = 0.f;

#pragma unroll
    for (int ni = 0; ni < 8; ++ni) {
        int d0 = nwb + ni * 8 + 2 * (lid & 3);
        float qb0 = c_qwb[d0], qb1 = c_qwb[d0 + 1];
        float w00 = c_cw0[d0], w01 = c_cw0[d0 + 1];
        float w10 = c_cw1[d0], w11 = c_cw1[d0 + 1];
        float w20 = c_cw2[d0], w21 = c_cw2[d0 + 1];
        float sw0 = c_sw[d0],  sw1 = c_sw[d0 + 1];
#pragma unroll
        for (int mi = 0; mi < 4; ++mi)
#pragma unroll
            for (int h = 0; h < 2; ++h) {
                int pi = mi * 2 + h;
                float x0 = acc[mi][ni][h * 2] + qb0
                         + e0r[pi] * w00 + e1r[pi] * w10 + e2r[pi] * w20;
                float x1 = acc[mi][ni][h * 2 + 1] + qb1
                         + e0r[pi] * w01 + e1r[pi] * w11 + e2r[pi] * w21;
                part[pi] = fmaf(tanh_fast(x0), sw0,
                                fmaf(tanh_fast(x1), sw1, part[pi]));
            }
    }
#pragma unroll
    for (int pi = 0; pi < 8; ++pi) {
        part[pi] += __shfl_xor_sync(0xffffffffu, part[pi], 1);
        part[pi] += __shfl_xor_sync(0xffffffffu, part[pi], 2);
    }
    float* red = (float*)(smem + SM_RED);
    if ((lid & 3) == 0) {
#pragma unroll
        for (int mi = 0; mi < 4; ++mi)
#pragma unroll
            for (int h = 0; h < 2; ++h) {
                int r = mi * 16 + h * 8 + (lid >> 2);
                red[r * 8 + wid] = part[mi * 2 + h];
            }
    }
    __syncthreads();
    if (tid < 64) {
        float sum = 0.f;   // score_b dropped: softmax shift-invariant
#pragma unroll
        for (int w = 0; w < 8; ++w) sum += red[tid * 8 + w];
        g_scores[b * SS + s0 + tid] = sum;
    }
}

// ============================================================================
// softmax per batch -> align; also zeroes ctx[b] (context runs after).
// ============================================================================
__global__ void softmax_kernel(float* __restrict__ align_out,
                               float* __restrict__ ctx) {
    __shared__ float wred[8];
    int b = blockIdx.x, t = threadIdx.x, w = t >> 5, l = t & 31;
    // zero this batch's ctx slice (512 floats)
    ((float2*)(ctx + b * DD))[t] = make_float2(0.f, 0.f);

    const float4* s4 = (const float4*)(g_scores + b * SS);
    float4 v0 = s4[t];
    float4 v1 = s4[t + 256];
    float m = fmaxf(fmaxf(fmaxf(v0.x, v0.y), fmaxf(v0.z, v0.w)),
                    fmaxf(fmaxf(v1.x, v1.y), fmaxf(v1.z, v1.w)));
#pragma unroll
    for (int o = 16; o > 0; o >>= 1)
        m = fmaxf(m, __shfl_xor_sync(0xffffffffu, m, o));
    if (l == 0) wred[w] = m;
    __syncthreads();
    m = wred[0];
#pragma unroll
    for (int i = 1; i < 8; ++i) m = fmaxf(m, wred[i]);
    __syncthreads();

    float4 e0, e1;
    e0.x = __expf(v0.x - m); e0.y = __expf(v0.y - m);
    e0.z = __expf(v0.z - m); e0.w = __expf(v0.w - m);
    e1.x = __expf(v1.x - m); e1.y = __expf(v1.y - m);
    e1.z = __expf(v1.z - m); e1.w = __expf(v1.w - m);
    float sum = e0.x + e0.y + e0.z + e0.w + e1.x + e1.y + e1.z + e1.w;
#pragma unroll
    for (int o = 16; o > 0; o >>= 1)
        sum += __shfl_xor_sync(0xffffffffu, sum, o);
    if (l == 0) wred[w] = sum;
    __syncthreads();
    sum = wred[0];
#pragma unroll
    for (int i = 1; i < 8; ++i) sum += wred[i];
    float inv = 1.f / sum;
    e0.x *= inv; e0.y *= inv; e0.z *= inv; e0.w *= inv;
    e1.x *= inv; e1.y *= inv; e1.z *= inv; e1.w *= inv;
    float4* a4 = (float4*)(align_out + b * SS);
    a4[t] = e0;
    a4[t + 256] = e1;
}

// ============================================================================
// context: ctx[b,d] = sum_s align[b,s] * value[b,s,d]   (R4-proven)
// ============================================================================
__global__ void context_kernel(const float* __restrict__ value,
                               const float* __restrict__ align,
                               float* __restrict__ ctx) {
    int b = blockIdx.x, dch = blockIdx.y, sch = blockIdx.z;
    int d = dch * 128 + threadIdx.x;
    const float* vb = value + ((size_t)b * SS + sch * 256) * DD + d;
    const float* ab = align + b * SS + sch * 256;
    float acc = 0.f;
#pragma unroll 8
    for (int s = 0; s < 256; ++s)
        acc = fmaf(ab[s], vb[(size_t)s * DD], acc);
    atomicAdd(&ctx[b * DD + d], acc);
}

// ============================================================================
// launch (4 kernels)
// ============================================================================
extern "C" void kernel_launch(void* const* d_in, const int* in_sizes, int n_in,
                              void* d_out, int out_size) {
    const float* query   = (const float*)d_in[0];
    const float* value   = (const float*)d_in[1];
    const float* energy  = (const float*)d_in[2];
    const float* conv_w  = (const float*)d_in[3];
    const float* conv_b  = (const float*)d_in[4];
    const float* w_q     = (const float*)d_in[5];
    const float* w_v     = (const float*)d_in[6];
    const float* bias    = (const float*)d_in[7];
    const float* score_w = (const float*)d_in[8];
    float* out_ctx   = (float*)d_out;            // [B*D]
    float* out_align = (float*)d_out + BB * DD;  // [B*S]

    cudaFuncSetAttribute(scores_kernel,
                         cudaFuncAttributeMaxDynamicSharedMemorySize, SM_TOT);

    prep_kernel<<<576, 256>>>(w_v, query, w_q, bias, conv_b);
    scores_kernel<<<BB * 32, 256, SM_TOT>>>(value, energy, conv_w, score_w);
    softmax_kernel<<<BB, 256>>>(out_align, out_ctx);
    context_kernel<<<dim3(BB, DD / 128, SS / 256), 128>>>(value, out_align,
                                                          out_ctx);
}

// round 14
// speedup vs baseline: 1.4295x; 1.0072x over previous
#include <cuda_runtime.h>
#include <cuda_fp16.h>
#include <cstdint>

// ============================================================================
// LocationAwareAttention  B=32, S=2048, D=512   (family-common PTX only:
// mma.sync + ldmatrix + cp.async — NO tcgen05, target is sm_103)
//
// R14: context kernel vectorized (float4 loads, smem-staged align, 4-deep
// unroll). R13 ncu: context 29.9us @ 58.6% DRAM, issue 13.6% -> MLP-limited.
// Everything else = R13-proven (157.2us total).
// Output: d_out = [ctx (B*D) | align (B*S)] fp32
// ============================================================================

#define BB 32
#define SS 2048
#define DD 512

__device__ __half g_wvt[DD * DD];          // w_v^T [n][k] fp16
__device__ float  g_qw_part[8 * BB * DD];  // k-split partials of q@w_q(+bias)
__device__ float  g_scores[BB * SS];

// ---------------- SMEM layout (bytes) ----------------
#define SM_A    0                      // 8 chunks x (64x64 fp16, swizzled) = 64KB
#define SM_B    65536                  // 8 warps x 2 stages x 8KB = 128KB
#define SM_QWB  196608
#define SM_CW0  198656
#define SM_CW1  200704
#define SM_CW2  202752
#define SM_SW   204800
#define SM_E0   206848
#define SM_E1   207104
#define SM_E2   207360
#define SM_RED  207616                 // 64 x 8 f32
#define SM_TOT  209664

// ---------------- PTX helpers ----------------
__device__ __forceinline__ uint32_t s2u(const void* p) {
    uint32_t a;
    asm("{ .reg .u64 t; cvta.to.shared.u64 t, %1; cvt.u32.u64 %0, t; }"
        : "=r"(a) : "l"(p));
    return a;
}
__device__ __forceinline__ void cp16(uint32_t dst, const void* src) {
    asm volatile("cp.async.ca.shared.global [%0], [%1], 16;"
                 :: "r"(dst), "l"(src) : "memory");
}
__device__ __forceinline__ void cp_commit() {
    asm volatile("cp.async.commit_group;" ::: "memory");
}
__device__ __forceinline__ void cp_wait0() {
    asm volatile("cp.async.wait_group 0;" ::: "memory");
}
__device__ __forceinline__ void cp_wait1() {
    asm volatile("cp.async.wait_group 1;" ::: "memory");
}
__device__ __forceinline__ void ldsm4(uint32_t& r0, uint32_t& r1,
                                      uint32_t& r2, uint32_t& r3, uint32_t a) {
    asm volatile("ldmatrix.sync.aligned.m8n8.x4.shared.b16 {%0,%1,%2,%3}, [%4];"
                 : "=r"(r0), "=r"(r1), "=r"(r2), "=r"(r3) : "r"(a));
}
__device__ __forceinline__ void mma16816(float* d, const uint32_t* a,
                                         const uint32_t* b) {
    asm volatile(
        "mma.sync.aligned.m16n8k16.row.col.f32.f16.f16.f32 "
        "{%0,%1,%2,%3}, {%4,%5,%6,%7}, {%8,%9}, {%0,%1,%2,%3};"
        : "+f"(d[0]), "+f"(d[1]), "+f"(d[2]), "+f"(d[3])
        : "r"(a[0]), "r"(a[1]), "r"(a[2]), "r"(a[3]), "r"(b[0]), "r"(b[1]));
}
__device__ __forceinline__ float tanh_fast(float x) {
    float y;
    asm("tanh.approx.f32 %0, %1;" : "=f"(y) : "f"(x));
    return y;
}
__device__ __forceinline__ uint32_t packh(__half a, __half b) {
    __half2 h2; h2.x = a; h2.y = b;
    return *(uint32_t*)&h2;
}
__device__ __forceinline__ uint32_t swz(uint32_t row, uint32_t colByte) {
    return row * 128u + (colByte ^ ((row & 7u) << 4));
}

// ============================================================================
// prep (R13-proven): 576 blocks x 256 threads.
// ============================================================================
__global__ void __launch_bounds__(256)
prep_kernel(const float* __restrict__ w_v,
            const float* __restrict__ query,
            const float* __restrict__ w_q,
            const float* __restrict__ bias,
            const float* __restrict__ conv_b) {
    const int blk = blockIdx.x, tid = threadIdx.x;
    if (blk < 64) {
        __shared__ float tile[64][65];
        const int ti = blk >> 3, tj = blk & 7;
#pragma unroll
        for (int q = 0; q < 4; ++q) {
            int idx = q * 256 + tid;
            int r = idx >> 4, c4 = idx & 15;
            float4 v = *(const float4*)(w_v + (size_t)(ti * 64 + r) * DD
                                        + tj * 64 + c4 * 4);
            tile[r][c4 * 4 + 0] = v.x;
            tile[r][c4 * 4 + 1] = v.y;
            tile[r][c4 * 4 + 2] = v.z;
            tile[r][c4 * 4 + 3] = v.w;
        }
        __syncthreads();
#pragma unroll
        for (int q = 0; q < 8; ++q) {
            int slot = q * 256 + tid;
            int nr = slot >> 5, kc = slot & 31;
            __half2 h = __floats2half2_rn(tile[kc * 2][nr],
                                          tile[kc * 2 + 1][nr]);
            *(__half2*)(g_wvt + (size_t)(tj * 64 + nr) * DD + ti * 64 + kc * 2) = h;
        }
    } else {
        const int bb = blk - 64;
        const int ks = bb & 7;
        const int dh = (bb >> 3) & 1;
        const int b  = bb >> 4;
        const int d  = dh * 256 + tid;
        const float* q = query + b * DD + ks * 64;
        const float* w = w_q + (size_t)(ks * 64) * DD + d;
        float a0 = 0.f, a1 = 0.f, a2 = 0.f, a3 = 0.f;
        float a4 = 0.f, a5 = 0.f, a6 = 0.f, a7 = 0.f;
#pragma unroll
        for (int k = 0; k < 64; k += 8) {
            a0 = fmaf(__ldg(q + k),     __ldg(w + (size_t)(k)     * DD), a0);
            a1 = fmaf(__ldg(q + k + 1), __ldg(w + (size_t)(k + 1) * DD), a1);
            a2 = fmaf(__ldg(q + k + 2), __ldg(w + (size_t)(k + 2) * DD), a2);
            a3 = fmaf(__ldg(q + k + 3), __ldg(w + (size_t)(k + 3) * DD), a3);
            a4 = fmaf(__ldg(q + k + 4), __ldg(w + (size_t)(k + 4) * DD), a4);
            a5 = fmaf(__ldg(q + k + 5), __ldg(w + (size_t)(k + 5) * DD), a5);
            a6 = fmaf(__ldg(q + k + 6), __ldg(w + (size_t)(k + 6) * DD), a6);
            a7 = fmaf(__ldg(q + k + 7), __ldg(w + (size_t)(k + 7) * DD), a7);
        }
        float sum = ((a0 + a1) + (a2 + a3)) + ((a4 + a5) + (a6 + a7));
        if (ks == 0) sum += bias[d] + conv_b[d];
        g_qw_part[(ks * BB + b) * DD + d] = sum;
    }
}

// ============================================================================
// scores (R13-proven, byte-identical)
// ============================================================================
__global__ void __launch_bounds__(256, 1)
scores_kernel(const float* __restrict__ value,
              const float* __restrict__ energy,
              const float* __restrict__ conv_w,
              const float* __restrict__ score_w) {
    extern __shared__ char smem[];
    const uint32_t sb = s2u(smem);
    const int tid = threadIdx.x, wid = tid >> 5, lid = tid & 31;
    const int b = blockIdx.x >> 5, tile = blockIdx.x & 31;
    const int s0 = tile * 64;
    const size_t grow0 = (size_t)b * SS + s0;
    const int nwb = wid * 64;

    auto cpB = [&](int ch) {
        const int kb = ch * 64;
        const uint32_t bbuf = sb + SM_B
                            + (uint32_t)((wid << 1) + (ch & 1)) * 8192u;
#pragma unroll
        for (int q = 0; q < 16; ++q) {
            int t = lid + q * 32, n = t >> 3, c = t & 7;
            cp16(bbuf + swz((uint32_t)n, (uint32_t)c * 16),
                 g_wvt + (size_t)(nwb + n) * DD + kb + c * 8);
        }
        cp_commit();
    };

    cpB(0);
    cpB(1);

    float* c_qwb = (float*)(smem + SM_QWB);
    float* c_cw0 = (float*)(smem + SM_CW0);
    float* c_cw1 = (float*)(smem + SM_CW1);
    float* c_cw2 = (float*)(smem + SM_CW2);
    float* c_sw  = (float*)(smem + SM_SW);
    for (int d = tid; d < DD; d += 256) {
        float qsum = 0.f;
#pragma unroll
        for (int ks = 0; ks < 8; ++ks)
            qsum += g_qw_part[(ks * BB + b) * DD + d];
        c_qwb[d] = qsum;
        c_cw0[d] = conv_w[d * 3 + 0];
        c_cw1[d] = conv_w[d * 3 + 1];
        c_cw2[d] = conv_w[d * 3 + 2];
        c_sw[d]  = score_w[d];
    }
    if (tid < 64) {
        int s = s0 + tid, gs = b * SS + s;
        ((float*)(smem + SM_E1))[tid] = energy[gs];
        ((float*)(smem + SM_E0))[tid] = (s > 0)      ? energy[gs - 1] : 0.f;
        ((float*)(smem + SM_E2))[tid] = (s < SS - 1) ? energy[gs + 1] : 0.f;
    }

#pragma unroll
    for (int ch = 0; ch < 8; ++ch) {
        const int kb = ch * 64;
        char* ah = smem + SM_A + ch * 8192;
#pragma unroll
        for (int q = 0; q < 2; ++q) {
            int t = tid * 2 + q, r = t >> 3, c = t & 7;
            const float4* src =
                (const float4*)(value + (grow0 + r) * DD + kb + c * 8);
            float4 v0 = src[0], v1 = src[1];
            uint4 hh;
            hh.x = packh(__float2half_rn(v0.x), __float2half_rn(v0.y));
            hh.y = packh(__float2half_rn(v0.z), __float2half_rn(v0.w));
            hh.z = packh(__float2half_rn(v1.x), __float2half_rn(v1.y));
            hh.w = packh(__float2half_rn(v1.z), __float2half_rn(v1.w));
            *(uint4*)(ah + swz((uint32_t)r, (uint32_t)c * 16)) = hh;
        }
    }
    __syncthreads();

    float acc[4][8][4];
#pragma unroll
    for (int i = 0; i < 4; ++i)
#pragma unroll
        for (int j = 0; j < 8; ++j)
#pragma unroll
            for (int c = 0; c < 4; ++c) acc[i][j][c] = 0.f;

    auto compute = [&](int ch) {
        const uint32_t abuf = sb + SM_A + (uint32_t)ch * 8192u;
        const uint32_t bbuf = sb + SM_B
                            + (uint32_t)((wid << 1) + (ch & 1)) * 8192u;
#pragma unroll
        for (int s = 0; s < 4; ++s) {
            uint32_t bfr[8][2];
#pragma unroll
            for (int np = 0; np < 4; ++np) {
                uint32_t row = np * 16 + ((lid & 16) >> 1) + (lid & 7);
                uint32_t col = s * 32 + ((lid & 8) << 1);
                ldsm4(bfr[np * 2][0], bfr[np * 2][1],
                      bfr[np * 2 + 1][0], bfr[np * 2 + 1][1],
                      bbuf + swz(row, col));
            }
#pragma unroll
            for (int mi = 0; mi < 4; ++mi) {
                uint32_t row = mi * 16 + (lid & 15);
                uint32_t col = s * 32 + (lid & 16);
                uint32_t ah[4];
                ldsm4(ah[0], ah[1], ah[2], ah[3], abuf + swz(row, col));
#pragma unroll
                for (int ni = 0; ni < 8; ++ni)
                    mma16816(acc[mi][ni], ah, bfr[ni]);
            }
        }
    };

    for (int ch = 0; ch < 8; ++ch) {
        if (ch < 7) cp_wait1();
        else        cp_wait0();
        __syncwarp();
        compute(ch);
        if (ch < 6) cpB(ch + 2);
    }

    const float* E0 = (const float*)(smem + SM_E0);
    const float* E1 = (const float*)(smem + SM_E1);
    const float* E2 = (const float*)(smem + SM_E2);
    float e0r[8], e1r[8], e2r[8];
#pragma unroll
    for (int mi = 0; mi < 4; ++mi)
#pragma unroll
        for (int h = 0; h < 2; ++h) {
            int r = mi * 16 + h * 8 + (lid >> 2);
            e0r[mi * 2 + h] = E0[r];
            e1r[mi * 2 + h] = E1[r];
            e2r[mi * 2 + h] = E2[r];
        }
    float part[8];
#pragma unroll
    for (int i = 0; i < 8; ++i) part[i] = 0.f;

#pragma unroll
    for (int ni = 0; ni < 8; ++ni) {
        int d0 = nwb + ni * 8 + 2 * (lid & 3);
        float qb0 = c_qwb[d0], qb1 = c_qwb[d0 + 1];
        float w00 = c_cw0[d0], w01 = c_cw0[d0 + 1];
        float w10 = c_cw1[d0], w11 = c_cw1[d0 + 1];
        float w20 = c_cw2[d0], w21 = c_cw2[d0 + 1];
        float sw0 = c_sw[d0],  sw1 = c_sw[d0 + 1];
#pragma unroll
        for (int mi = 0; mi < 4; ++mi)
#pragma unroll
            for (int h = 0; h < 2; ++h) {
                int pi = mi * 2 + h;
                float x0 = acc[mi][ni][h * 2] + qb0
                         + e0r[pi] * w00 + e1r[pi] * w10 + e2r[pi] * w20;
                float x1 = acc[mi][ni][h * 2 + 1] + qb1
                         + e0r[pi] * w01 + e1r[pi] * w11 + e2r[pi] * w21;
                part[pi] = fmaf(tanh_fast(x0), sw0,
                                fmaf(tanh_fast(x1), sw1, part[pi]));
            }
    }
#pragma unroll
    for (int pi = 0; pi < 8; ++pi) {
        part[pi] += __shfl_xor_sync(0xffffffffu, part[pi], 1);
        part[pi] += __shfl_xor_sync(0xffffffffu, part[pi], 2);
    }
    float* red = (float*)(smem + SM_RED);
    if ((lid & 3) == 0) {
#pragma unroll
        for (int mi = 0; mi < 4; ++mi)
#pragma unroll
            for (int h = 0; h < 2; ++h) {
                int r = mi * 16 + h * 8 + (lid >> 2);
                red[r * 8 + wid] = part[mi * 2 + h];
            }
    }
    __syncthreads();
    if (tid < 64) {
        float sum = 0.f;
#pragma unroll
        for (int w = 0; w < 8; ++w) sum += red[tid * 8 + w];
        g_scores[b * SS + s0 + tid] = sum;
    }
}

// ============================================================================
// softmax per batch -> align; also zeroes ctx[b] (context runs after).
// ============================================================================
__global__ void softmax_kernel(float* __restrict__ align_out,
                               float* __restrict__ ctx) {
    __shared__ float wred[8];
    int b = blockIdx.x, t = threadIdx.x, w = t >> 5, l = t & 31;
    ((float2*)(ctx + b * DD))[t] = make_float2(0.f, 0.f);

    const float4* s4 = (const float4*)(g_scores + b * SS);
    float4 v0 = s4[t];
    float4 v1 = s4[t + 256];
    float m = fmaxf(fmaxf(fmaxf(v0.x, v0.y), fmaxf(v0.z, v0.w)),
                    fmaxf(fmaxf(v1.x, v1.y), fmaxf(v1.z, v1.w)));
#pragma unroll
    for (int o = 16; o > 0; o >>= 1)
        m = fmaxf(m, __shfl_xor_sync(0xffffffffu, m, o));
    if (l == 0) wred[w] = m;
    __syncthreads();
    m = wred[0];
#pragma unroll
    for (int i = 1; i < 8; ++i) m = fmaxf(m, wred[i]);
    __syncthreads();

    float4 e0, e1;
    e0.x = __expf(v0.x - m); e0.y = __expf(v0.y - m);
    e0.z = __expf(v0.z - m); e0.w = __expf(v0.w - m);
    e1.x = __expf(v1.x - m); e1.y = __expf(v1.y - m);
    e1.z = __expf(v1.z - m); e1.w = __expf(v1.w - m);
    float sum = e0.x + e0.y + e0.z + e0.w + e1.x + e1.y + e1.z + e1.w;
#pragma unroll
    for (int o = 16; o > 0; o >>= 1)
        sum += __shfl_xor_sync(0xffffffffu, sum, o);
    if (l == 0) wred[w] = sum;
    __syncthreads();
    sum = wred[0];
#pragma unroll
    for (int i = 1; i < 8; ++i) sum += wred[i];
    float inv = 1.f / sum;
    e0.x *= inv; e0.y *= inv; e0.z *= inv; e0.w *= inv;
    e1.x *= inv; e1.y *= inv; e1.z *= inv; e1.w *= inv;
    float4* a4 = (float4*)(align_out + b * SS);
    a4[t] = e0;
    a4[t + 256] = e1;
}

// ============================================================================
// context v2: float4 loads, smem-staged align, 4-deep unroll.
// Grid (B, 16): block handles 128 s-rows x all 512 d-cols.
// Thread t covers cols [4t, 4t+4).
// ============================================================================
__global__ void __launch_bounds__(128)
context_kernel(const float* __restrict__ value,
               const float* __restrict__ align,
               float* __restrict__ ctx) {
    __shared__ float al[128];
    const int b = blockIdx.x, sch = blockIdx.y;
    const int t = threadIdx.x;
    al[t] = align[b * SS + sch * 128 + t];
    __syncthreads();

    const float4* vb = (const float4*)(value
                        + ((size_t)b * SS + sch * 128) * DD) + t;
    float4 acc = make_float4(0.f, 0.f, 0.f, 0.f);
#pragma unroll 4
    for (int s = 0; s < 128; ++s) {
        float4 v = vb[(size_t)s * (DD / 4)];
        float a = al[s];
        acc.x = fmaf(a, v.x, acc.x);
        acc.y = fmaf(a, v.y, acc.y);
        acc.z = fmaf(a, v.z, acc.z);
        acc.w = fmaf(a, v.w, acc.w);
    }
    float* dst = ctx + b * DD + t * 4;
    atomicAdd(dst + 0, acc.x);
    atomicAdd(dst + 1, acc.y);
    atomicAdd(dst + 2, acc.z);
    atomicAdd(dst + 3, acc.w);
}

// ============================================================================
// launch (4 kernels)
// ============================================================================
extern "C" void kernel_launch(void* const* d_in, const int* in_sizes, int n_in,
                              void* d_out, int out_size) {
    const float* query   = (const float*)d_in[0];
    const float* value   = (const float*)d_in[1];
    const float* energy  = (const float*)d_in[2];
    const float* conv_w  = (const float*)d_in[3];
    const float* conv_b  = (const float*)d_in[4];
    const float* w_q     = (const float*)d_in[5];
    const float* w_v     = (const float*)d_in[6];
    const float* bias    = (const float*)d_in[7];
    const float* score_w = (const float*)d_in[8];
    float* out_ctx   = (float*)d_out;            // [B*D]
    float* out_align = (float*)d_out + BB * DD;  // [B*S]

    cudaFuncSetAttribute(scores_kernel,
                         cudaFuncAttributeMaxDynamicSharedMemorySize, SM_TOT);

    prep_kernel<<<576, 256>>>(w_v, query, w_q, bias, conv_b);
    scores_kernel<<<BB * 32, 256, SM_TOT>>>(value, energy, conv_w, score_w);
    softmax_kernel<<<BB, 256>>>(out_align, out_ctx);
    context_kernel<<<dim3(BB, 16), 128>>>(value, out_align, out_ctx);
}

// round 15
// speedup vs baseline: 1.4919x; 1.0436x over previous
#include <cuda_runtime.h>
#include <cuda_fp16.h>
#include <cstdint>

// ============================================================================
// LocationAwareAttention  B=32, S=2048, D=512   (family-common PTX only:
// mma.sync + ldmatrix + cp.async — NO tcgen05, target is sm_103)
//
// R15: context occupancy fix. R14 ncu: context still 29.9us @58.7% DRAM,
// occ 20.3% (512 blocks x 4 warps caps loads-in-flight). Now grid (B,32) x
// 256 threads = 1024 blocks, ~55 warps/SM -> DRAM concurrency ~5x.
// Everything else = R14 (156.1us).
// Output: d_out = [ctx (B*D) | align (B*S)] fp32
// ============================================================================

#define BB 32
#define SS 2048
#define DD 512

__device__ __half g_wvt[DD * DD];          // w_v^T [n][k] fp16
__device__ float  g_qw_part[8 * BB * DD];  // k-split partials of q@w_q(+bias)
__device__ float  g_scores[BB * SS];

// ---------------- SMEM layout (bytes) ----------------
#define SM_A    0                      // 8 chunks x (64x64 fp16, swizzled) = 64KB
#define SM_B    65536                  // 8 warps x 2 stages x 8KB = 128KB
#define SM_QWB  196608
#define SM_CW0  198656
#define SM_CW1  200704
#define SM_CW2  202752
#define SM_SW   204800
#define SM_E0   206848
#define SM_E1   207104
#define SM_E2   207360
#define SM_RED  207616                 // 64 x 8 f32
#define SM_TOT  209664

// ---------------- PTX helpers ----------------
__device__ __forceinline__ uint32_t s2u(const void* p) {
    uint32_t a;
    asm("{ .reg .u64 t; cvta.to.shared.u64 t, %1; cvt.u32.u64 %0, t; }"
        : "=r"(a) : "l"(p));
    return a;
}
__device__ __forceinline__ void cp16(uint32_t dst, const void* src) {
    asm volatile("cp.async.ca.shared.global [%0], [%1], 16;"
                 :: "r"(dst), "l"(src) : "memory");
}
__device__ __forceinline__ void cp_commit() {
    asm volatile("cp.async.commit_group;" ::: "memory");
}
__device__ __forceinline__ void cp_wait0() {
    asm volatile("cp.async.wait_group 0;" ::: "memory");
}
__device__ __forceinline__ void cp_wait1() {
    asm volatile("cp.async.wait_group 1;" ::: "memory");
}
__device__ __forceinline__ void ldsm4(uint32_t& r0, uint32_t& r1,
                                      uint32_t& r2, uint32_t& r3, uint32_t a) {
    asm volatile("ldmatrix.sync.aligned.m8n8.x4.shared.b16 {%0,%1,%2,%3}, [%4];"
                 : "=r"(r0), "=r"(r1), "=r"(r2), "=r"(r3) : "r"(a));
}
__device__ __forceinline__ void mma16816(float* d, const uint32_t* a,
                                         const uint32_t* b) {
    asm volatile(
        "mma.sync.aligned.m16n8k16.row.col.f32.f16.f16.f32 "
        "{%0,%1,%2,%3}, {%4,%5,%6,%7}, {%8,%9}, {%0,%1,%2,%3};"
        : "+f"(d[0]), "+f"(d[1]), "+f"(d[2]), "+f"(d[3])
        : "r"(a[0]), "r"(a[1]), "r"(a[2]), "r"(a[3]), "r"(b[0]), "r"(b[1]));
}
__device__ __forceinline__ float tanh_fast(float x) {
    float y;
    asm("tanh.approx.f32 %0, %1;" : "=f"(y) : "f"(x));
    return y;
}
__device__ __forceinline__ uint32_t packh(__half a, __half b) {
    __half2 h2; h2.x = a; h2.y = b;
    return *(uint32_t*)&h2;
}
__device__ __forceinline__ uint32_t swz(uint32_t row, uint32_t colByte) {
    return row * 128u + (colByte ^ ((row & 7u) << 4));
}

// ============================================================================
// prep (R13-proven): 576 blocks x 256 threads.
// ============================================================================
__global__ void __launch_bounds__(256)
prep_kernel(const float* __restrict__ w_v,
            const float* __restrict__ query,
            const float* __restrict__ w_q,
            const float* __restrict__ bias,
            const float* __restrict__ conv_b) {
    const int blk = blockIdx.x, tid = threadIdx.x;
    if (blk < 64) {
        __shared__ float tile[64][65];
        const int ti = blk >> 3, tj = blk & 7;
#pragma unroll
        for (int q = 0; q < 4; ++q) {
            int idx = q * 256 + tid;
            int r = idx >> 4, c4 = idx & 15;
            float4 v = *(const float4*)(w_v + (size_t)(ti * 64 + r) * DD
                                        + tj * 64 + c4 * 4);
            tile[r][c4 * 4 + 0] = v.x;
            tile[r][c4 * 4 + 1] = v.y;
            tile[r][c4 * 4 + 2] = v.z;
            tile[r][c4 * 4 + 3] = v.w;
        }
        __syncthreads();
#pragma unroll
        for (int q = 0; q < 8; ++q) {
            int slot = q * 256 + tid;
            int nr = slot >> 5, kc = slot & 31;
            __half2 h = __floats2half2_rn(tile[kc * 2][nr],
                                          tile[kc * 2 + 1][nr]);
            *(__half2*)(g_wvt + (size_t)(tj * 64 + nr) * DD + ti * 64 + kc * 2) = h;
        }
    } else {
        const int bb = blk - 64;
        const int ks = bb & 7;
        const int dh = (bb >> 3) & 1;
        const int b  = bb >> 4;
        const int d  = dh * 256 + tid;
        const float* q = query + b * DD + ks * 64;
        const float* w = w_q + (size_t)(ks * 64) * DD + d;
        float a0 = 0.f, a1 = 0.f, a2 = 0.f, a3 = 0.f;
        float a4 = 0.f, a5 = 0.f, a6 = 0.f, a7 = 0.f;
#pragma unroll
        for (int k = 0; k < 64; k += 8) {
            a0 = fmaf(__ldg(q + k),     __ldg(w + (size_t)(k)     * DD), a0);
            a1 = fmaf(__ldg(q + k + 1), __ldg(w + (size_t)(k + 1) * DD), a1);
            a2 = fmaf(__ldg(q + k + 2), __ldg(w + (size_t)(k + 2) * DD), a2);
            a3 = fmaf(__ldg(q + k + 3), __ldg(w + (size_t)(k + 3) * DD), a3);
            a4 = fmaf(__ldg(q + k + 4), __ldg(w + (size_t)(k + 4) * DD), a4);
            a5 = fmaf(__ldg(q + k + 5), __ldg(w + (size_t)(k + 5) * DD), a5);
            a6 = fmaf(__ldg(q + k + 6), __ldg(w + (size_t)(k + 6) * DD), a6);
            a7 = fmaf(__ldg(q + k + 7), __ldg(w + (size_t)(k + 7) * DD), a7);
        }
        float sum = ((a0 + a1) + (a2 + a3)) + ((a4 + a5) + (a6 + a7));
        if (ks == 0) sum += bias[d] + conv_b[d];
        g_qw_part[(ks * BB + b) * DD + d] = sum;
    }
}

// ============================================================================
// scores (R13-proven, byte-identical)
// ============================================================================
__global__ void __launch_bounds__(256, 1)
scores_kernel(const float* __restrict__ value,
              const float* __restrict__ energy,
              const float* __restrict__ conv_w,
              const float* __restrict__ score_w) {
    extern __shared__ char smem[];
    const uint32_t sb = s2u(smem);
    const int tid = threadIdx.x, wid = tid >> 5, lid = tid & 31;
    const int b = blockIdx.x >> 5, tile = blockIdx.x & 31;
    const int s0 = tile * 64;
    const size_t grow0 = (size_t)b * SS + s0;
    const int nwb = wid * 64;

    auto cpB = [&](int ch) {
        const int kb = ch * 64;
        const uint32_t bbuf = sb + SM_B
                            + (uint32_t)((wid << 1) + (ch & 1)) * 8192u;
#pragma unroll
        for (int q = 0; q < 16; ++q) {
            int t = lid + q * 32, n = t >> 3, c = t & 7;
            cp16(bbuf + swz((uint32_t)n, (uint32_t)c * 16),
                 g_wvt + (size_t)(nwb + n) * DD + kb + c * 8);
        }
        cp_commit();
    };

    cpB(0);
    cpB(1);

    float* c_qwb = (float*)(smem + SM_QWB);
    float* c_cw0 = (float*)(smem + SM_CW0);
    float* c_cw1 = (float*)(smem + SM_CW1);
    float* c_cw2 = (float*)(smem + SM_CW2);
    float* c_sw  = (float*)(smem + SM_SW);
    for (int d = tid; d < DD; d += 256) {
        float qsum = 0.f;
#pragma unroll
        for (int ks = 0; ks < 8; ++ks)
            qsum += g_qw_part[(ks * BB + b) * DD + d];
        c_qwb[d] = qsum;
        c_cw0[d] = conv_w[d * 3 + 0];
        c_cw1[d] = conv_w[d * 3 + 1];
        c_cw2[d] = conv_w[d * 3 + 2];
        c_sw[d]  = score_w[d];
    }
    if (tid < 64) {
        int s = s0 + tid, gs = b * SS + s;
        ((float*)(smem + SM_E1))[tid] = energy[gs];
        ((float*)(smem + SM_E0))[tid] = (s > 0)      ? energy[gs - 1] : 0.f;
        ((float*)(smem + SM_E2))[tid] = (s < SS - 1) ? energy[gs + 1] : 0.f;
    }

#pragma unroll
    for (int ch = 0; ch < 8; ++ch) {
        const int kb = ch * 64;
        char* ah = smem + SM_A + ch * 8192;
#pragma unroll
        for (int q = 0; q < 2; ++q) {
            int t = tid * 2 + q, r = t >> 3, c = t & 7;
            const float4* src =
                (const float4*)(value + (grow0 + r) * DD + kb + c * 8);
            float4 v0 = src[0], v1 = src[1];
            uint4 hh;
            hh.x = packh(__float2half_rn(v0.x), __float2half_rn(v0.y));
            hh.y = packh(__float2half_rn(v0.z), __float2half_rn(v0.w));
            hh.z = packh(__float2half_rn(v1.x), __float2half_rn(v1.y));
            hh.w = packh(__float2half_rn(v1.z), __float2half_rn(v1.w));
            *(uint4*)(ah + swz((uint32_t)r, (uint32_t)c * 16)) = hh;
        }
    }
    __syncthreads();

    float acc[4][8][4];
#pragma unroll
    for (int i = 0; i < 4; ++i)
#pragma unroll
        for (int j = 0; j < 8; ++j)
#pragma unroll
            for (int c = 0; c < 4; ++c) acc[i][j][c] = 0.f;

    auto compute = [&](int ch) {
        const uint32_t abuf = sb + SM_A + (uint32_t)ch * 8192u;
        const uint32_t bbuf = sb + SM_B
                            + (uint32_t)((wid << 1) + (ch & 1)) * 8192u;
#pragma unroll
        for (int s = 0; s < 4; ++s) {
            uint32_t bfr[8][2];
#pragma unroll
            for (int np = 0; np < 4; ++np) {
                uint32_t row = np * 16 + ((lid & 16) >> 1) + (lid & 7);
                uint32_t col = s * 32 + ((lid & 8) << 1);
                ldsm4(bfr[np * 2][0], bfr[np * 2][1],
                      bfr[np * 2 + 1][0], bfr[np * 2 + 1][1],
                      bbuf + swz(row, col));
            }
#pragma unroll
            for (int mi = 0; mi < 4; ++mi) {
                uint32_t row = mi * 16 + (lid & 15);
                uint32_t col = s * 32 + (lid & 16);
                uint32_t ah[4];
                ldsm4(ah[0], ah[1], ah[2], ah[3], abuf + swz(row, col));
#pragma unroll
                for (int ni = 0; ni < 8; ++ni)
                    mma16816(acc[mi][ni], ah, bfr[ni]);
            }
        }
    };

    for (int ch = 0; ch < 8; ++ch) {
        if (ch < 7) cp_wait1();
        else        cp_wait0();
        __syncwarp();
        compute(ch);
        if (ch < 6) cpB(ch + 2);
    }

    const float* E0 = (const float*)(smem + SM_E0);
    const float* E1 = (const float*)(smem + SM_E1);
    const float* E2 = (const float*)(smem + SM_E2);
    float e0r[8], e1r[8], e2r[8];
#pragma unroll
    for (int mi = 0; mi < 4; ++mi)
#pragma unroll
        for (int h = 0; h < 2; ++h) {
            int r = mi * 16 + h * 8 + (lid >> 2);
            e0r[mi * 2 + h] = E0[r];
            e1r[mi * 2 + h] = E1[r];
            e2r[mi * 2 + h] = E2[r];
        }
    float part[8];
#pragma unroll
    for (int i = 0; i < 8; ++i) part[i] = 0.f;

#pragma unroll
    for (int ni = 0; ni < 8; ++ni) {
        int d0 = nwb + ni * 8 + 2 * (lid & 3);
        float qb0 = c_qwb[d0], qb1 = c_qwb[d0 + 1];
        float w00 = c_cw0[d0], w01 = c_cw0[d0 + 1];
        float w10 = c_cw1[d0], w11 = c_cw1[d0 + 1];
        float w20 = c_cw2[d0], w21 = c_cw2[d0 + 1];
        float sw0 = c_sw[d0],  sw1 = c_sw[d0 + 1];
#pragma unroll
        for (int mi = 0; mi < 4; ++mi)
#pragma unroll
            for (int h = 0; h < 2; ++h) {
                int pi = mi * 2 + h;
                float x0 = acc[mi][ni][h * 2] + qb0
                         + e0r[pi] * w00 + e1r[pi] * w10 + e2r[pi] * w20;
                float x1 = acc[mi][ni][h * 2 + 1] + qb1
                         + e0r[pi] * w01 + e1r[pi] * w11 + e2r[pi] * w21;
                part[pi] = fmaf(tanh_fast(x0), sw0,
                                fmaf(tanh_fast(x1), sw1, part[pi]));
            }
    }
#pragma unroll
    for (int pi = 0; pi < 8; ++pi) {
        part[pi] += __shfl_xor_sync(0xffffffffu, part[pi], 1);
        part[pi] += __shfl_xor_sync(0xffffffffu, part[pi], 2);
    }
    float* red = (float*)(smem + SM_RED);
    if ((lid & 3) == 0) {
#pragma unroll
        for (int mi = 0; mi < 4; ++mi)
#pragma unroll
            for (int h = 0; h < 2; ++h) {
                int r = mi * 16 + h * 8 + (lid >> 2);
                red[r * 8 + wid] = part[mi * 2 + h];
            }
    }
    __syncthreads();
    if (tid < 64) {
        float sum = 0.f;
#pragma unroll
        for (int w = 0; w < 8; ++w) sum += red[tid * 8 + w];
        g_scores[b * SS + s0 + tid] = sum;
    }
}

// ============================================================================
// softmax per batch -> align; also zeroes ctx[b] (context runs after).
// ============================================================================
__global__ void softmax_kernel(float* __restrict__ align_out,
                               float* __restrict__ ctx) {
    __shared__ float wred[8];
    int b = blockIdx.x, t = threadIdx.x, w = t >> 5, l = t & 31;
    ((float2*)(ctx + b * DD))[t] = make_float2(0.f, 0.f);

    const float4* s4 = (const float4*)(g_scores + b * SS);
    float4 v0 = s4[t];
    float4 v1 = s4[t + 256];
    float m = fmaxf(fmaxf(fmaxf(v0.x, v0.y), fmaxf(v0.z, v0.w)),
                    fmaxf(fmaxf(v1.x, v1.y), fmaxf(v1.z, v1.w)));
#pragma unroll
    for (int o = 16; o > 0; o >>= 1)
        m = fmaxf(m, __shfl_xor_sync(0xffffffffu, m, o));
    if (l == 0) wred[w] = m;
    __syncthreads();
    m = wred[0];
#pragma unroll
    for (int i = 1; i < 8; ++i) m = fmaxf(m, wred[i]);
    __syncthreads();

    float4 e0, e1;
    e0.x = __expf(v0.x - m); e0.y = __expf(v0.y - m);
    e0.z = __expf(v0.z - m); e0.w = __expf(v0.w - m);
    e1.x = __expf(v1.x - m); e1.y = __expf(v1.y - m);
    e1.z = __expf(v1.z - m); e1.w = __expf(v1.w - m);
    float sum = e0.x + e0.y + e0.z + e0.w + e1.x + e1.y + e1.z + e1.w;
#pragma unroll
    for (int o = 16; o > 0; o >>= 1)
        sum += __shfl_xor_sync(0xffffffffu, sum, o);
    if (l == 0) wred[w] = sum;
    __syncthreads();
    sum = wred[0];
#pragma unroll
    for (int i = 1; i < 8; ++i) sum += wred[i];
    float inv = 1.f / sum;
    e0.x *= inv; e0.y *= inv; e0.z *= inv; e0.w *= inv;
    e1.x *= inv; e1.y *= inv; e1.z *= inv; e1.w *= inv;
    float4* a4 = (float4*)(align_out + b * SS);
    a4[t] = e0;
    a4[t + 256] = e1;
}

// ============================================================================
// context v3: grid (B, 32 s-chunks) x 256 threads (occupancy-driven MLP).
// Block handles 64 s-rows x 512 d-cols; thread t covers cols [4*(t&127), +4),
// s-half = t>>7 (32 rows each). Block smem reduction -> 512 atomics/block.
// ============================================================================
__global__ void __launch_bounds__(256)
context_kernel(const float* __restrict__ value,
               const float* __restrict__ align,
               float* __restrict__ ctx) {
    __shared__ float al[64];
    __shared__ float4 pc[256];
    const int b = blockIdx.x, sch = blockIdx.y;
    const int t = threadIdx.x;
    if (t < 64) al[t] = align[b * SS + sch * 64 + t];
    __syncthreads();

    const int ct = t & 127;            // col group: cols [4*ct, 4*ct+4)
    const int sh = t >> 7;             // s-half: rows [sh*32, sh*32+32)
    const float4* vb = (const float4*)(value
                        + ((size_t)b * SS + sch * 64 + sh * 32) * DD) + ct;
    const float* ab = al + sh * 32;
    float4 acc = make_float4(0.f, 0.f, 0.f, 0.f);
#pragma unroll 8
    for (int s = 0; s < 32; ++s) {
        float4 v = vb[(size_t)s * (DD / 4)];
        float a = ab[s];
        acc.x = fmaf(a, v.x, acc.x);
        acc.y = fmaf(a, v.y, acc.y);
        acc.z = fmaf(a, v.z, acc.z);
        acc.w = fmaf(a, v.w, acc.w);
    }
    pc[t] = acc;
    __syncthreads();
    if (t < 128) {
        float4 p0 = pc[t], p1 = pc[t + 128];
        float* dst = ctx + b * DD + t * 4;
        atomicAdd(dst + 0, p0.x + p1.x);
        atomicAdd(dst + 1, p0.y + p1.y);
        atomicAdd(dst + 2, p0.z + p1.z);
        atomicAdd(dst + 3, p0.w + p1.w);
    }
}

// ============================================================================
// launch (4 kernels)
// ============================================================================
extern "C" void kernel_launch(void* const* d_in, const int* in_sizes, int n_in,
                              void* d_out, int out_size) {
    const float* query   = (const float*)d_in[0];
    const float* value   = (const float*)d_in[1];
    const float* energy  = (const float*)d_in[2];
    const float* conv_w  = (const float*)d_in[3];
    const float* conv_b  = (const float*)d_in[4];
    const float* w_q     = (const float*)d_in[5];
    const float* w_v     = (const float*)d_in[6];
    const float* bias    = (const float*)d_in[7];
    const float* score_w = (const float*)d_in[8];
    float* out_ctx   = (float*)d_out;            // [B*D]
    float* out_align = (float*)d_out + BB * DD;  // [B*S]

    cudaFuncSetAttribute(scores_kernel,
                         cudaFuncAttributeMaxDynamicSharedMemorySize, SM_TOT);

    prep_kernel<<<576, 256>>>(w_v, query, w_q, bias, conv_b);
    scores_kernel<<<BB * 32, 256, SM_TOT>>>(value, energy, conv_w, score_w);
    softmax_kernel<<<BB, 256>>>(out_align, out_ctx);
    context_kernel<<<dim3(BB, 32), 256>>>(value, out_align, out_ctx);
}